// round 8
// baseline (speedup 1.0000x reference)
#include <cuda_runtime.h>
#include <cuda_fp16.h>
#include <cstdint>
#include <cstddef>

#define Bsz 4
#define Tseq 2048
#define Dm 512
#define Hh 8
#define FFd 2048
#define NLAYER 4
#define ROWS (Bsz*Tseq)   /* 8192 */

// ---------------- scratch (device globals; no allocations allowed) ----------
__device__ __align__(128) float g_x [ROWS*Dm];
__device__ __align__(128) __half g_q [ROWS*3*Dm];
__device__ __align__(128) __half g_xa[ROWS*Dm];
__device__ __align__(128) __half g_a [ROWS*Dm];
__device__ __align__(128) __half g_f [ROWS*FFd];
__device__ __align__(128) __half g_wq[NLAYER*3*Dm*Dm];
__device__ __align__(128) __half g_wo[NLAYER*Dm*Dm];
__device__ __align__(128) __half g_w1[NLAYER*FFd*Dm];
__device__ __align__(128) __half g_w2[NLAYER*Dm*FFd];

// ---------------- helpers ----------------------------------------------------
__device__ __forceinline__ void cp16(uint32_t s, const void* g) {
    asm volatile("cp.async.cg.shared.global [%0], [%1], 16;" :: "r"(s), "l"(g));
}
__device__ __forceinline__ void cp_commit() {
    asm volatile("cp.async.commit_group;" ::: "memory");
}
template<int N> __device__ __forceinline__ void cp_wait() {
    asm volatile("cp.async.wait_group %0;" :: "n"(N) : "memory");
}
__device__ __forceinline__ void ldsm4(uint32_t* r, uint32_t addr) {
    asm volatile("ldmatrix.sync.aligned.m8n8.x4.shared.b16 {%0,%1,%2,%3}, [%4];"
                 : "=r"(r[0]), "=r"(r[1]), "=r"(r[2]), "=r"(r[3]) : "r"(addr));
}
__device__ __forceinline__ void mma16816(float* c, const uint32_t* a, const uint32_t* b) {
    asm volatile(
        "mma.sync.aligned.m16n8k16.row.col.f32.f16.f16.f32 "
        "{%0,%1,%2,%3}, {%4,%5,%6,%7}, {%8,%9}, {%0,%1,%2,%3};"
        : "+f"(c[0]), "+f"(c[1]), "+f"(c[2]), "+f"(c[3])
        : "r"(a[0]), "r"(a[1]), "r"(a[2]), "r"(a[3]), "r"(b[0]), "r"(b[1]));
}

// ---------------- weight fp32 -> fp16 convert --------------------------------
__global__ __launch_bounds__(256)
void cvt4_kernel(const float* __restrict__ w, __half* __restrict__ h, int n4) {
    int i = blockIdx.x * 256 + threadIdx.x;
    if (i < n4) {
        float4 v = ((const float4*)w)[i];
        ((__half2*)h)[i*2]     = __floats2half2_rn(v.x, v.y);
        ((__half2*)h)[i*2 + 1] = __floats2half2_rn(v.z, v.w);
    }
}

// ---------------- HMMA GEMM (generic): C[M,N] = A[M,K] @ W[N,K]^T ------------
// BM=128, BN=256, BK=32, 256 threads (8 warps, warp tile 64x64), 3-stage cp.async.
// MODE 2: Ch = fp16(relu(acc + bias))
// MODE 3: Ch = fp16(acc + bias)
#define AROW 80
#define A_TILE (128*AROW)
#define B_TILE (256*AROW)
#define STAGE_B (A_TILE + B_TILE)
#define NSTAGE 3
#define GS_TOTAL (NSTAGE*STAGE_B)

__device__ __forceinline__ void gload(uint32_t st,
    const __half* __restrict__ A, const __half* __restrict__ B,
    int bm, int bn, int K, int k0, int tid)
{
    #pragma unroll
    for (int i = 0; i < 2; i++) {
        int idx = tid + i * 256;
        int row = idx >> 2, c = idx & 3;
        cp16(st + (uint32_t)(row * AROW + c * 16), A + (size_t)(bm + row) * K + k0 + c * 8);
    }
    #pragma unroll
    for (int i = 0; i < 4; i++) {
        int idx = tid + i * 256;
        int row = idx >> 2, c = idx & 3;
        cp16(st + A_TILE + (uint32_t)(row * AROW + c * 16), B + (size_t)(bn + row) * K + k0 + c * 8);
    }
    cp_commit();
}

template<int MODE>
__global__ __launch_bounds__(256, 1)
void tc_gemm(const __half* __restrict__ A, const __half* __restrict__ B,
             const float* __restrict__ bias, __half* __restrict__ Ch,
             int M, int N, int K)
{
    extern __shared__ __align__(128) char smem[];
    uint32_t sb = (uint32_t)__cvta_generic_to_shared(smem);
    int tid = threadIdx.x;
    int wid = tid >> 5, lane = tid & 31;
    int bn = blockIdx.x * 256, bm = blockIdx.y * 128;
    int wm = (wid & 1) * 64;
    int wn = (wid >> 1) * 64;

    float acc[4][8][4];
    #pragma unroll
    for (int i = 0; i < 4; i++)
        #pragma unroll
        for (int j = 0; j < 8; j++)
            #pragma unroll
            for (int r = 0; r < 4; r++) acc[i][j][r] = 0.f;

    const int C = K >> 5;
    gload(sb,           A, B, bm, bn, K, 0,  tid);
    gload(sb + STAGE_B, A, B, bm, bn, K, 32, tid);

    uint32_t a_row = (uint32_t)(lane & 15);
    uint32_t a_koff = (uint32_t)((lane >> 4) * 16);
    uint32_t b_row = (uint32_t)((lane & 7) + ((lane >> 4) << 3));
    uint32_t b_koff = (uint32_t)(((lane >> 3) & 1) * 16);

    for (int c = 0; c < C; c++) {
        if (c + 1 < C) cp_wait<1>(); else cp_wait<0>();
        __syncthreads();
        if (c + 2 < C)
            gload(sb + ((c + 2) % NSTAGE) * STAGE_B, A, B, bm, bn, K, (c + 2) * 32, tid);

        uint32_t sa = sb + (c % NSTAGE) * STAGE_B;
        #pragma unroll
        for (int kk = 0; kk < 2; kk++) {
            uint32_t kb = (uint32_t)(kk * 32);
            uint32_t af[4][4];
            #pragma unroll
            for (int mt = 0; mt < 4; mt++)
                ldsm4(af[mt], sa + (wm + mt*16 + a_row) * AROW + kb + a_koff);
            #pragma unroll
            for (int ng = 0; ng < 4; ng++) {
                uint32_t bf[4];
                ldsm4(bf, sa + A_TILE + (wn + ng*16 + b_row) * AROW + kb + b_koff);
                #pragma unroll
                for (int mt = 0; mt < 4; mt++)
                    #pragma unroll
                    for (int half = 0; half < 2; half++)
                        mma16816(acc[mt][ng*2 + half], af[mt], &bf[half*2]);
            }
        }
    }

    #pragma unroll
    for (int mt = 0; mt < 4; mt++) {
        int m0 = bm + wm + mt*16 + (lane >> 2);
        #pragma unroll
        for (int nt = 0; nt < 8; nt++) {
            int n = bn + wn + nt*8 + (lane & 3)*2;
            float bx = bias[n], by = bias[n+1];
            #pragma unroll
            for (int h = 0; h < 2; h++) {
                int m = m0 + h*8;
                float v0 = acc[mt][nt][h*2]   + bx;
                float v1 = acc[mt][nt][h*2+1] + by;
                if (MODE == 2) { v0 = fmaxf(v0, 0.f); v1 = fmaxf(v1, 0.f); }
                *(__half2*)(Ch + (size_t)m * N + n) = __floats2half2_rn(v0, v1);
            }
        }
    }
}

// ---------------- HMMA GEMM + residual + LayerNorm (N=512) -------------------
// BM=64, BN=512 (full row per CTA), 256 threads, warp tile 32x128, 3 stages.
// out: fp32 LN result (x or d_out); oh: fp16 LN result (null on last layer).
#define A_TILE2 (64*AROW)            /* 5120 */
#define B_TILE2 (512*AROW)           /* 40960 */
#define STAGE2  (A_TILE2 + B_TILE2)  /* 46080 */
#define GS2_TOTAL (NSTAGE*STAGE2)    /* 138240 */

__device__ __forceinline__ void gload2(uint32_t st,
    const __half* __restrict__ A, const __half* __restrict__ B,
    int bm, int K, int k0, int tid)
{
    {
        int row = tid >> 2, c = tid & 3;
        cp16(st + (uint32_t)(row * AROW + c * 16), A + (size_t)(bm + row) * K + k0 + c * 8);
    }
    #pragma unroll
    for (int i = 0; i < 8; i++) {
        int idx = tid + i * 256;
        int row = idx >> 2, c = idx & 3;
        cp16(st + A_TILE2 + (uint32_t)(row * AROW + c * 16), B + (size_t)row * K + k0 + c * 8);
    }
    cp_commit();
}

__global__ __launch_bounds__(256, 1)
void tc_gemm_ln(const __half* __restrict__ A, const __half* __restrict__ B,
                const float* __restrict__ bias, const float* __restrict__ res,
                const float* __restrict__ gam, const float* __restrict__ bet,
                float* __restrict__ outf, __half* __restrict__ outh, int K)
{
    extern __shared__ __align__(128) char smem[];
    uint32_t sb = (uint32_t)__cvta_generic_to_shared(smem);
    int tid = threadIdx.x;
    int wid = tid >> 5, lane = tid & 31;
    int bm = blockIdx.y * 64;
    int wm = (wid & 1) * 32;
    int wn = (wid >> 1) * 128;

    float acc[2][16][4];
    #pragma unroll
    for (int i = 0; i < 2; i++)
        #pragma unroll
        for (int j = 0; j < 16; j++)
            #pragma unroll
            for (int r = 0; r < 4; r++) acc[i][j][r] = 0.f;

    const int C = K >> 5;
    gload2(sb,          A, B, bm, K, 0,  tid);
    gload2(sb + STAGE2, A, B, bm, K, 32, tid);

    uint32_t a_row = (uint32_t)(lane & 15);
    uint32_t a_koff = (uint32_t)((lane >> 4) * 16);
    uint32_t b_row = (uint32_t)((lane & 7) + ((lane >> 4) << 3));
    uint32_t b_koff = (uint32_t)(((lane >> 3) & 1) * 16);

    for (int c = 0; c < C; c++) {
        if (c + 1 < C) cp_wait<1>(); else cp_wait<0>();
        __syncthreads();
        if (c + 2 < C)
            gload2(sb + ((c + 2) % NSTAGE) * STAGE2, A, B, bm, K, (c + 2) * 32, tid);

        uint32_t sa = sb + (c % NSTAGE) * STAGE2;
        #pragma unroll
        for (int kk = 0; kk < 2; kk++) {
            uint32_t kb = (uint32_t)(kk * 32);
            uint32_t af[2][4];
            #pragma unroll
            for (int mt = 0; mt < 2; mt++)
                ldsm4(af[mt], sa + (wm + mt*16 + a_row) * AROW + kb + a_koff);
            #pragma unroll
            for (int ng = 0; ng < 8; ng++) {
                uint32_t bf[4];
                ldsm4(bf, sa + A_TILE2 + (wn + ng*16 + b_row) * AROW + kb + b_koff);
                #pragma unroll
                for (int mt = 0; mt < 2; mt++)
                    #pragma unroll
                    for (int half = 0; half < 2; half++)
                        mma16816(acc[mt][ng*2 + half], af[mt], &bf[half*2]);
            }
        }
    }

    // ---- epilogue: bias + residual, then LayerNorm over the 512-col row ----
    __syncthreads();                      // smem about to be reused for partials
    float* psum = (float*)smem;           // [64 rows][4 warp-cols]
    float* psq  = psum + 256;

    // add bias + residual, accumulate row partials
    float rsums[2][2], rsqs[2][2];
    #pragma unroll
    for (int mt = 0; mt < 2; mt++)
        #pragma unroll
        for (int h = 0; h < 2; h++) {
            float s = 0.f, sq = 0.f;
            int m = bm + wm + mt*16 + (lane >> 2) + h*8;
            #pragma unroll
            for (int nt = 0; nt < 16; nt++) {
                int n = wn + nt*8 + (lane & 3)*2;
                float2 rv = *(const float2*)&res[(size_t)m * 512 + n];
                float v0 = acc[mt][nt][h*2]   + bias[n]   + rv.x;
                float v1 = acc[mt][nt][h*2+1] + bias[n+1] + rv.y;
                acc[mt][nt][h*2]   = v0;
                acc[mt][nt][h*2+1] = v1;
                s  += v0 + v1;
                sq += v0*v0 + v1*v1;
            }
            // reduce across the 4 lanes sharing this row
            s  += __shfl_xor_sync(0xffffffffu, s, 1);
            s  += __shfl_xor_sync(0xffffffffu, s, 2);
            sq += __shfl_xor_sync(0xffffffffu, sq, 1);
            sq += __shfl_xor_sync(0xffffffffu, sq, 2);
            rsums[mt][h] = s; rsqs[mt][h] = sq;
            if ((lane & 3) == 0) {
                int rloc = wm + mt*16 + (lane >> 2) + h*8;
                psum[rloc*4 + (wid >> 1)] = s;
                psq [rloc*4 + (wid >> 1)] = sq;
            }
        }
    __syncthreads();

    #pragma unroll
    for (int mt = 0; mt < 2; mt++)
        #pragma unroll
        for (int h = 0; h < 2; h++) {
            int rloc = wm + mt*16 + (lane >> 2) + h*8;
            int m = bm + rloc;
            float ts = psum[rloc*4] + psum[rloc*4+1] + psum[rloc*4+2] + psum[rloc*4+3];
            float tq = psq [rloc*4] + psq [rloc*4+1] + psq [rloc*4+2] + psq [rloc*4+3];
            float mean = ts * (1.0f/512.0f);
            float var  = tq * (1.0f/512.0f) - mean*mean;
            float inv  = rsqrtf(var + 1e-5f);
            #pragma unroll
            for (int nt = 0; nt < 16; nt++) {
                int n = wn + nt*8 + (lane & 3)*2;
                float v0 = (acc[mt][nt][h*2]   - mean) * inv * gam[n]   + bet[n];
                float v1 = (acc[mt][nt][h*2+1] - mean) * inv * gam[n+1] + bet[n+1];
                *(float2*)&outf[(size_t)m * 512 + n] = make_float2(v0, v1);
                if (outh)
                    *(__half2*)(outh + (size_t)m * 512 + n) = __floats2half2_rn(v0, v1);
            }
        }
}

// ---------------- tensor-core banded attention (fp16) ------------------------
#define OFF_QH 0
#define OFF_KH 9216    /* also VT in phase C */
#define OFF_S  18432   /* fp32 [64][328] */
#define OFF_PH 102400  /* fp16 [64][344] */
#define ATT_SMEM 146432

__global__ __launch_bounds__(256, 1)
void attn_tc(const __half* __restrict__ q, __half* __restrict__ outp)
{
    extern __shared__ __align__(128) char smraw[];
    uint32_t sb = (uint32_t)__cvta_generic_to_shared(smraw);
    float* S = (float*)(smraw + OFF_S);

    int tid = threadIdx.x;
    int wid = tid >> 5, lane = tid & 31;
    int b = blockIdx.z, h = blockIdx.y;
    int qstart = blockIdx.x << 6;
    size_t rowbase = (size_t)b * Tseq;
    int wm = (wid & 1) * 32;
    int wn = (wid >> 1) * 16;

    uint32_t a_row = (uint32_t)(lane & 15);
    uint32_t a_koff = (uint32_t)((lane >> 4) * 16);
    uint32_t b_row = (uint32_t)((lane & 7) + ((lane >> 4) << 3));
    uint32_t b_koff = (uint32_t)(((lane >> 3) & 1) * 16);

    #pragma unroll
    for (int r = 0; r < 2; r++) {
        int idx = tid + r*256;
        int qi = idx >> 3, seg = idx & 7;
        size_t go = (rowbase + qstart + qi)*1536 + h*64 + seg*8;
        *(uint4*)(smraw + OFF_QH + qi*144 + seg*16) = *(const uint4*)(q + go);
    }
    __syncthreads();

    uint32_t af[2][4][4];
    #pragma unroll
    for (int mt = 0; mt < 2; mt++)
        #pragma unroll
        for (int ks = 0; ks < 4; ks++)
            ldsm4(af[mt][ks], sb + OFF_QH + (wm + mt*16 + a_row)*144 + ks*32 + a_koff);

    const float scale = 0.125f;

    for (int kb = 0; kb < 5; kb++) {
        __syncthreads();
        #pragma unroll
        for (int r = 0; r < 2; r++) {
            int idx = tid + r*256;
            int kj = idx >> 3, seg = idx & 7;
            int ka = qstart - 128 + kb*64 + kj;
            uint4 v = make_uint4(0,0,0,0);
            if (ka >= 0 && ka < Tseq)
                v = *(const uint4*)(q + (rowbase + ka)*1536 + 512 + h*64 + seg*8);
            *(uint4*)(smraw + OFF_KH + kj*144 + seg*16) = v;
        }
        __syncthreads();

        float acc[2][2][4];
        #pragma unroll
        for (int i = 0; i < 2; i++)
            #pragma unroll
            for (int j = 0; j < 2; j++)
                #pragma unroll
                for (int r = 0; r < 4; r++) acc[i][j][r] = 0.f;

        #pragma unroll
        for (int ks = 0; ks < 4; ks++) {
            uint32_t bf[4];
            ldsm4(bf, sb + OFF_KH + (wn + b_row)*144 + ks*32 + b_koff);
            #pragma unroll
            for (int mt = 0; mt < 2; mt++)
                #pragma unroll
                for (int half = 0; half < 2; half++)
                    mma16816(acc[mt][half], af[mt][ks], &bf[half*2]);
        }

        #pragma unroll
        for (int mt = 0; mt < 2; mt++)
            #pragma unroll
            for (int half = 0; half < 2; half++)
                #pragma unroll
                for (int r = 0; r < 4; r++) {
                    int qi   = wm + mt*16 + (lane >> 2) + (r >> 1)*8;
                    int kidx = kb*64 + wn + half*8 + (lane & 3)*2 + (r & 1);
                    int ka   = qstart - 128 + kidx;
                    int delta = kidx - qi;
                    bool ok = (delta >= 0) && (delta <= 256) && (ka >= 0) && (ka < Tseq);
                    S[qi*328 + kidx] = ok ? acc[mt][half][r] * scale : -1e30f;
                }
    }
    __syncthreads();

    {
        __half* PH = (__half*)(smraw + OFF_PH);
        for (int qq = wid*8; qq < wid*8 + 8; qq++) {
            float v[10]; float m = -1e30f;
            #pragma unroll
            for (int i = 0; i < 10; i++) { v[i] = S[qq*328 + lane + i*32]; m = fmaxf(m, v[i]); }
            #pragma unroll
            for (int o = 16; o > 0; o >>= 1) m = fmaxf(m, __shfl_xor_sync(0xffffffffu, m, o));
            float ssum = 0.f;
            #pragma unroll
            for (int i = 0; i < 10; i++) { v[i] = __expf(v[i] - m); ssum += v[i]; }
            #pragma unroll
            for (int o = 16; o > 0; o >>= 1) ssum += __shfl_xor_sync(0xffffffffu, ssum, o);
            float rs = 1.0f / ssum;
            #pragma unroll
            for (int i = 0; i < 10; i++)
                PH[qq*344 + lane + i*32] = __float2half(v[i] * rs);
        }
    }

    float oacc[2][2][4];
    #pragma unroll
    for (int i = 0; i < 2; i++)
        #pragma unroll
        for (int j = 0; j < 2; j++)
            #pragma unroll
            for (int r = 0; r < 4; r++) oacc[i][j][r] = 0.f;

    for (int kb = 0; kb < 5; kb++) {
        __syncthreads();
        #pragma unroll
        for (int r = 0; r < 2; r++) {
            int idx = tid + r*256;
            int kj = idx >> 3, seg = idx & 7;
            int d0 = seg * 8;
            int ka = qstart - 128 + kb*64 + kj;
            union U8 { uint4 u; __half e[8]; } v;
            v.u = make_uint4(0,0,0,0);
            if (ka >= 0 && ka < Tseq)
                v.u = *(const uint4*)(q + (rowbase + ka)*1536 + 1024 + h*64 + d0);
            __half* VT = (__half*)(smraw + OFF_KH);
            #pragma unroll
            for (int j = 0; j < 8; j++)
                VT[(d0 + j)*72 + kj] = v.e[j];
        }
        __syncthreads();

        #pragma unroll
        for (int ks = 0; ks < 4; ks++) {
            uint32_t aP[2][4];
            #pragma unroll
            for (int mt = 0; mt < 2; mt++)
                ldsm4(aP[mt], sb + OFF_PH + (wm + mt*16 + a_row)*688 + (kb*64 + ks*16)*2 + a_koff);
            uint32_t bf[4];
            ldsm4(bf, sb + OFF_KH + (wn + b_row)*144 + ks*32 + b_koff);
            #pragma unroll
            for (int mt = 0; mt < 2; mt++)
                #pragma unroll
                for (int half = 0; half < 2; half++)
                    mma16816(oacc[mt][half], aP[mt], &bf[half*2]);
        }
    }

    #pragma unroll
    for (int mt = 0; mt < 2; mt++)
        #pragma unroll
        for (int half = 0; half < 2; half++)
            #pragma unroll
            for (int hr = 0; hr < 2; hr++) {
                int qi = wm + mt*16 + (lane >> 2) + hr*8;
                int d  = wn + half*8 + (lane & 3)*2;
                size_t idx = (rowbase + qstart + qi)*512 + h*64 + d;
                *(__half2*)(outp + idx) =
                    __floats2half2_rn(oacc[mt][half][hr*2], oacc[mt][half][hr*2+1]);
            }
}

// ---------------- input projection ------------------------------------------
__global__ __launch_bounds__(128)
void inproj_kernel(const float* __restrict__ feat, const float* __restrict__ w,
                   const float* __restrict__ bias, const float* __restrict__ pe,
                   float* __restrict__ out, __half* __restrict__ oh)
{
    int row = blockIdx.x;
    int t = row & (Tseq - 1);
    __shared__ float f[32];
    if (threadIdx.x < 32) f[threadIdx.x] = feat[(size_t)row*32 + threadIdx.x];
    __syncthreads();
    int d0 = threadIdx.x * 4;
    float a[4];
    #pragma unroll
    for (int j = 0; j < 4; j++) a[j] = bias[d0 + j];
    #pragma unroll
    for (int j = 0; j < 4; j++) {
        const float4* wp = (const float4*)(w + (size_t)(d0 + j) * 32);
        #pragma unroll
        for (int k4 = 0; k4 < 8; k4++) {
            float4 wv = wp[k4];
            a[j] += wv.x*f[k4*4] + wv.y*f[k4*4+1] + wv.z*f[k4*4+2] + wv.w*f[k4*4+3];
        }
    }
    float4 pev = *(const float4*)(pe + (size_t)t*512 + d0);
    float4 r = make_float4(a[0]+pev.x, a[1]+pev.y, a[2]+pev.z, a[3]+pev.w);
    *(float4*)(out + (size_t)row*512 + d0) = r;
    *(__half2*)(oh + (size_t)row*512 + d0)     = __floats2half2_rn(r.x, r.y);
    *(__half2*)(oh + (size_t)row*512 + d0 + 2) = __floats2half2_rn(r.z, r.w);
}

// ---------------- launch ----------------------------------------------------
extern "C" void kernel_launch(void* const* d_in, const int* in_sizes, int n_in,
                              void* d_out, int out_size)
{
    const float* feat   = (const float*)d_in[0];
    const float* proj_w = (const float*)d_in[2];
    const float* proj_b = (const float*)d_in[3];
    const float* pe     = (const float*)d_in[4];
    const float* qkv_w  = (const float*)d_in[5];
    const float* qkv_b  = (const float*)d_in[6];
    const float* out_w  = (const float*)d_in[7];
    const float* out_b  = (const float*)d_in[8];
    const float* ff1_w  = (const float*)d_in[9];
    const float* ff1_b  = (const float*)d_in[10];
    const float* ff2_w  = (const float*)d_in[11];
    const float* ff2_b  = (const float*)d_in[12];
    const float* ln1_g  = (const float*)d_in[13];
    const float* ln1_b  = (const float*)d_in[14];
    const float* ln2_g  = (const float*)d_in[15];
    const float* ln2_b  = (const float*)d_in[16];

    float *x;
    __half *q, *xa, *a, *f, *wq, *wo, *w1, *w2;
    cudaGetSymbolAddress((void**)&x,  g_x);
    cudaGetSymbolAddress((void**)&q,  g_q);
    cudaGetSymbolAddress((void**)&xa, g_xa);
    cudaGetSymbolAddress((void**)&a,  g_a);
    cudaGetSymbolAddress((void**)&f,  g_f);
    cudaGetSymbolAddress((void**)&wq, g_wq);
    cudaGetSymbolAddress((void**)&wo, g_wo);
    cudaGetSymbolAddress((void**)&w1, g_w1);
    cudaGetSymbolAddress((void**)&w2, g_w2);

    cudaFuncSetAttribute(attn_tc,    cudaFuncAttributeMaxDynamicSharedMemorySize, ATT_SMEM);
    cudaFuncSetAttribute(tc_gemm<2>, cudaFuncAttributeMaxDynamicSharedMemorySize, GS_TOTAL);
    cudaFuncSetAttribute(tc_gemm<3>, cudaFuncAttributeMaxDynamicSharedMemorySize, GS_TOTAL);
    cudaFuncSetAttribute(tc_gemm_ln, cudaFuncAttributeMaxDynamicSharedMemorySize, GS2_TOTAL);

    {
        int n4;
        n4 = NLAYER*3*Dm*Dm/4; cvt4_kernel<<<(n4+255)/256,256>>>(qkv_w, wq, n4);
        n4 = NLAYER*Dm*Dm/4;   cvt4_kernel<<<(n4+255)/256,256>>>(out_w, wo, n4);
        n4 = NLAYER*FFd*Dm/4;  cvt4_kernel<<<(n4+255)/256,256>>>(ff1_w, w1, n4);
        n4 = NLAYER*Dm*FFd/4;  cvt4_kernel<<<(n4+255)/256,256>>>(ff2_w, w2, n4);
    }

    inproj_kernel<<<ROWS, 128>>>(feat, proj_w, proj_b, pe, x, xa);

    for (int l = 0; l < NLAYER; l++) {
        // QKV -> fp16
        tc_gemm<3><<<dim3(3*Dm/256, ROWS/128), 256, GS_TOTAL>>>(
            xa, wq + (size_t)l*3*Dm*Dm, qkv_b + (size_t)l*3*Dm, q, ROWS, 3*Dm, Dm);
        // banded attention -> a (fp16)
        attn_tc<<<dim3(Tseq/64, Hh, Bsz), 256, ATT_SMEM>>>(q, a);
        // out proj + residual(x) + LN1 -> x (fp32) + xa (fp16)
        tc_gemm_ln<<<dim3(1, ROWS/64), 256, GS2_TOTAL>>>(
            a, wo + (size_t)l*Dm*Dm, out_b + (size_t)l*Dm, x,
            ln1_g + (size_t)l*Dm, ln1_b + (size_t)l*Dm, x, xa, Dm);
        // FF1 + ReLU -> f (fp16)
        tc_gemm<2><<<dim3(FFd/256, ROWS/128), 256, GS_TOTAL>>>(
            xa, w1 + (size_t)l*FFd*Dm, ff1_b + (size_t)l*FFd, f, ROWS, FFd, Dm);
        // FF2 + residual(x) + LN2 -> x + xa (or d_out on last layer)
        if (l == NLAYER - 1)
            tc_gemm_ln<<<dim3(1, ROWS/64), 256, GS2_TOTAL>>>(
                f, w2 + (size_t)l*Dm*FFd, ff2_b + (size_t)l*Dm, x,
                ln2_g + (size_t)l*Dm, ln2_b + (size_t)l*Dm, (float*)d_out, nullptr, FFd);
        else
            tc_gemm_ln<<<dim3(1, ROWS/64), 256, GS2_TOTAL>>>(
                f, w2 + (size_t)l*Dm*FFd, ff2_b + (size_t)l*Dm, x,
                ln2_g + (size_t)l*Dm, ln2_b + (size_t)l*Dm, x, xa, FFd);
    }
}

// round 9
// speedup vs baseline: 1.1231x; 1.1231x over previous
#include <cuda_runtime.h>
#include <cuda_fp16.h>
#include <cstdint>
#include <cstddef>

#define Bsz 4
#define Tseq 2048
#define Dm 512
#define Hh 8
#define FFd 2048
#define NLAYER 4
#define ROWS (Bsz*Tseq)   /* 8192 */

// ---------------- scratch (device globals; no allocations allowed) ----------
__device__ __align__(128) float g_x [ROWS*Dm];
__device__ __align__(128) float g_y [ROWS*Dm];
__device__ __align__(128) __half g_q [ROWS*3*Dm];
__device__ __align__(128) __half g_xa[ROWS*Dm];
__device__ __align__(128) __half g_a [ROWS*Dm];
__device__ __align__(128) __half g_f [ROWS*FFd];
__device__ __align__(128) __half g_wq[NLAYER*3*Dm*Dm];
__device__ __align__(128) __half g_wo[NLAYER*Dm*Dm];
__device__ __align__(128) __half g_w1[NLAYER*FFd*Dm];
__device__ __align__(128) __half g_w2[NLAYER*Dm*FFd];

// ---------------- helpers ----------------------------------------------------
__device__ __forceinline__ void cp16(uint32_t s, const void* g) {
    asm volatile("cp.async.cg.shared.global [%0], [%1], 16;" :: "r"(s), "l"(g));
}
__device__ __forceinline__ void cp16z(uint32_t s, const void* g, int sz) {
    asm volatile("cp.async.cg.shared.global [%0], [%1], 16, %2;" :: "r"(s), "l"(g), "r"(sz));
}
__device__ __forceinline__ void cp_commit() {
    asm volatile("cp.async.commit_group;" ::: "memory");
}
template<int N> __device__ __forceinline__ void cp_wait() {
    asm volatile("cp.async.wait_group %0;" :: "n"(N) : "memory");
}
__device__ __forceinline__ void ldsm4(uint32_t* r, uint32_t addr) {
    asm volatile("ldmatrix.sync.aligned.m8n8.x4.shared.b16 {%0,%1,%2,%3}, [%4];"
                 : "=r"(r[0]), "=r"(r[1]), "=r"(r[2]), "=r"(r[3]) : "r"(addr));
}
__device__ __forceinline__ void ldsm4t(uint32_t* r, uint32_t addr) {
    asm volatile("ldmatrix.sync.aligned.m8n8.x4.trans.shared.b16 {%0,%1,%2,%3}, [%4];"
                 : "=r"(r[0]), "=r"(r[1]), "=r"(r[2]), "=r"(r[3]) : "r"(addr));
}
__device__ __forceinline__ void mma16816(float* c, const uint32_t* a, const uint32_t* b) {
    asm volatile(
        "mma.sync.aligned.m16n8k16.row.col.f32.f16.f16.f32 "
        "{%0,%1,%2,%3}, {%4,%5,%6,%7}, {%8,%9}, {%0,%1,%2,%3};"
        : "+f"(c[0]), "+f"(c[1]), "+f"(c[2]), "+f"(c[3])
        : "r"(a[0]), "r"(a[1]), "r"(a[2]), "r"(a[3]), "r"(b[0]), "r"(b[1]));
}

// ---------------- weight fp32 -> fp16 convert --------------------------------
__global__ __launch_bounds__(256)
void cvt4_kernel(const float* __restrict__ w, __half* __restrict__ h, int n4) {
    int i = blockIdx.x * 256 + threadIdx.x;
    if (i < n4) {
        float4 v = ((const float4*)w)[i];
        ((__half2*)h)[i*2]     = __floats2half2_rn(v.x, v.y);
        ((__half2*)h)[i*2 + 1] = __floats2half2_rn(v.z, v.w);
    }
}

// ---------------- HMMA GEMM: C[M,N] = A[M,K] @ W[N,K]^T ----------------------
// BM=128, BN=256, BK=32, 256 threads (8 warps, warp tile 64x64), 4-stage cp.async.
// MODE 0: Cf = acc + bias
// MODE 1: Cf = acc + bias + res
// MODE 2: Ch = fp16(relu(acc + bias))
// MODE 3: Ch = fp16(acc + bias)
#define AROW 80
#define A_TILE (128*AROW)
#define B_TILE (256*AROW)
#define STAGE_B (A_TILE + B_TILE)
#define NSTAGE 4
#define GS_TOTAL (NSTAGE*STAGE_B)   /* 122880 */

__device__ __forceinline__ void gload(uint32_t st,
    const __half* __restrict__ A, const __half* __restrict__ B,
    int bm, int bn, int K, int k0, int tid)
{
    #pragma unroll
    for (int i = 0; i < 2; i++) {
        int idx = tid + i * 256;
        int row = idx >> 2, c = idx & 3;
        cp16(st + (uint32_t)(row * AROW + c * 16), A + (size_t)(bm + row) * K + k0 + c * 8);
    }
    #pragma unroll
    for (int i = 0; i < 4; i++) {
        int idx = tid + i * 256;
        int row = idx >> 2, c = idx & 3;
        cp16(st + A_TILE + (uint32_t)(row * AROW + c * 16), B + (size_t)(bn + row) * K + k0 + c * 8);
    }
    cp_commit();
}

template<int MODE>
__global__ __launch_bounds__(256, 1)
void tc_gemm(const __half* __restrict__ A, const __half* __restrict__ B,
             const float* __restrict__ bias, const float* __restrict__ res,
             float* __restrict__ Cf, __half* __restrict__ Ch,
             int M, int N, int K)
{
    extern __shared__ __align__(128) char smem[];
    uint32_t sb = (uint32_t)__cvta_generic_to_shared(smem);
    int tid = threadIdx.x;
    int wid = tid >> 5, lane = tid & 31;
    int bn = blockIdx.x * 256, bm = blockIdx.y * 128;
    int wm = (wid & 1) * 64;
    int wn = (wid >> 1) * 64;

    float acc[4][8][4];
    #pragma unroll
    for (int i = 0; i < 4; i++)
        #pragma unroll
        for (int j = 0; j < 8; j++)
            #pragma unroll
            for (int r = 0; r < 4; r++) acc[i][j][r] = 0.f;

    const int C = K >> 5;
    gload(sb,             A, B, bm, bn, K, 0,  tid);
    gload(sb +   STAGE_B, A, B, bm, bn, K, 32, tid);
    gload(sb + 2*STAGE_B, A, B, bm, bn, K, 64, tid);

    uint32_t a_row = (uint32_t)(lane & 15);
    uint32_t a_koff = (uint32_t)((lane >> 4) * 16);
    uint32_t b_row = (uint32_t)((lane & 7) + ((lane >> 4) << 3));
    uint32_t b_koff = (uint32_t)(((lane >> 3) & 1) * 16);

    for (int c = 0; c < C; c++) {
        if (c + 2 < C) cp_wait<2>();
        else if (c + 1 < C) cp_wait<1>();
        else cp_wait<0>();
        __syncthreads();
        if (c + 3 < C)
            gload(sb + ((c + 3) % NSTAGE) * STAGE_B, A, B, bm, bn, K, (c + 3) * 32, tid);

        uint32_t sa = sb + (c % NSTAGE) * STAGE_B;
        #pragma unroll
        for (int kk = 0; kk < 2; kk++) {
            uint32_t kb = (uint32_t)(kk * 32);
            uint32_t af[4][4];
            #pragma unroll
            for (int mt = 0; mt < 4; mt++)
                ldsm4(af[mt], sa + (wm + mt*16 + a_row) * AROW + kb + a_koff);
            #pragma unroll
            for (int ng = 0; ng < 4; ng++) {
                uint32_t bf[4];
                ldsm4(bf, sa + A_TILE + (wn + ng*16 + b_row) * AROW + kb + b_koff);
                #pragma unroll
                for (int mt = 0; mt < 4; mt++)
                    #pragma unroll
                    for (int half = 0; half < 2; half++)
                        mma16816(acc[mt][ng*2 + half], af[mt], &bf[half*2]);
            }
        }
    }

    #pragma unroll
    for (int mt = 0; mt < 4; mt++) {
        int m0 = bm + wm + mt*16 + (lane >> 2);
        #pragma unroll
        for (int nt = 0; nt < 8; nt++) {
            int n = bn + wn + nt*8 + (lane & 3)*2;
            float bx = bias[n], by = bias[n+1];
            #pragma unroll
            for (int h = 0; h < 2; h++) {
                int m = m0 + h*8;
                float v0 = acc[mt][nt][h*2]   + bx;
                float v1 = acc[mt][nt][h*2+1] + by;
                size_t idx = (size_t)m * N + n;
                if (MODE == 1) {
                    float2 rv = *(const float2*)&res[idx];
                    v0 += rv.x; v1 += rv.y;
                }
                if (MODE == 2 || MODE == 3) {
                    if (MODE == 2) { v0 = fmaxf(v0, 0.f); v1 = fmaxf(v1, 0.f); }
                    *(__half2*)(Ch + idx) = __floats2half2_rn(v0, v1);
                } else {
                    *(float2*)&Cf[idx] = make_float2(v0, v1);
                }
            }
        }
    }
}

// ---------------- tensor-core banded attention (fp16, cp.async pipelined) ----
// K/V double-buffered via cp.async; V stored row-major, PV B-fragments via
// ldmatrix.trans. S fp32, softmax with 1/sum folded into fp16 P.
#define OFF_Q  0
#define OFF_K0 9216
#define OFF_K1 18432
#define OFF_S  27648    /* fp32 [64][328] = 83968 B */
#define OFF_P  111616   /* fp16 [64][344] = 44032 B */
#define ATT_SMEM 155648

__global__ __launch_bounds__(256, 1)
void attn_tc(const __half* __restrict__ q, __half* __restrict__ outp)
{
    extern __shared__ __align__(128) char smraw[];
    uint32_t sb = (uint32_t)__cvta_generic_to_shared(smraw);
    float* S = (float*)(smraw + OFF_S);

    int tid = threadIdx.x;
    int wid = tid >> 5, lane = tid & 31;
    int b = blockIdx.z, h = blockIdx.y;
    int qstart = blockIdx.x << 6;
    size_t rowbase = (size_t)b * Tseq;
    int wm = (wid & 1) * 32;
    int wn = (wid >> 1) * 16;

    uint32_t a_row = (uint32_t)(lane & 15);
    uint32_t a_koff = (uint32_t)((lane >> 4) * 16);
    uint32_t b_row = (uint32_t)((lane & 7) + ((lane >> 4) << 3));
    uint32_t b_koff = (uint32_t)(((lane >> 3) & 1) * 16);

    int fi = tid >> 3;          // 0..31 row (two rows per thread via r loop)
    int seg = tid & 7;

    // ---- group 0: Q tile + K block 0 ----
    #pragma unroll
    for (int r = 0; r < 2; r++) {
        int qi = fi + r*32;
        cp16(sb + OFF_Q + qi*144 + seg*16,
             q + (rowbase + qstart + qi)*1536 + h*64 + seg*8);
    }
    #pragma unroll
    for (int r = 0; r < 2; r++) {
        int kj = fi + r*32;
        int ka = qstart - 128 + kj;
        int kc = ka < 0 ? 0 : (ka >= Tseq ? Tseq-1 : ka);
        cp16z(sb + OFF_K0 + kj*144 + seg*16,
              q + (rowbase + kc)*1536 + 512 + h*64 + seg*8,
              (ka >= 0 && ka < Tseq) ? 16 : 0);
    }
    cp_commit();

    const float scale = 0.125f;
    uint32_t af[2][4][4];

    // ---- phase A: S = Q K^T over 5 key blocks (double-buffered) ----
    for (int kb = 0; kb < 5; kb++) {
        cp_wait<0>();
        __syncthreads();
        if (kb == 0) {
            #pragma unroll
            for (int mt = 0; mt < 2; mt++)
                #pragma unroll
                for (int ks = 0; ks < 4; ks++)
                    ldsm4(af[mt][ks], sb + OFF_Q + (wm + mt*16 + a_row)*144 + ks*32 + a_koff);
        }
        if (kb < 4) {
            uint32_t dstb = (kb + 1) & 1 ? OFF_K1 : OFF_K0;
            #pragma unroll
            for (int r = 0; r < 2; r++) {
                int kj = fi + r*32;
                int ka = qstart - 128 + (kb+1)*64 + kj;
                int kc = ka < 0 ? 0 : (ka >= Tseq ? Tseq-1 : ka);
                cp16z(sb + dstb + kj*144 + seg*16,
                      q + (rowbase + kc)*1536 + 512 + h*64 + seg*8,
                      (ka >= 0 && ka < Tseq) ? 16 : 0);
            }
            cp_commit();
        }

        uint32_t kbuf = sb + (kb & 1 ? OFF_K1 : OFF_K0);
        float acc[2][2][4];
        #pragma unroll
        for (int i = 0; i < 2; i++)
            #pragma unroll
            for (int j = 0; j < 2; j++)
                #pragma unroll
                for (int r = 0; r < 4; r++) acc[i][j][r] = 0.f;

        #pragma unroll
        for (int ks = 0; ks < 4; ks++) {
            uint32_t bf[4];
            ldsm4(bf, kbuf + (wn + b_row)*144 + ks*32 + b_koff);
            #pragma unroll
            for (int mt = 0; mt < 2; mt++)
                #pragma unroll
                for (int half = 0; half < 2; half++)
                    mma16816(acc[mt][half], af[mt][ks], &bf[half*2]);
        }

        // masked float2 stores to S
        #pragma unroll
        for (int mt = 0; mt < 2; mt++)
            #pragma unroll
            for (int half = 0; half < 2; half++)
                #pragma unroll
                for (int hr = 0; hr < 2; hr++) {
                    int qi   = wm + mt*16 + (lane >> 2) + hr*8;
                    int kidx = kb*64 + wn + half*8 + (lane & 3)*2;
                    int ka   = qstart - 128 + kidx;
                    int d0 = kidx - qi, d1 = kidx + 1 - qi;
                    bool ok0 = (d0 >= 0) && (d0 <= 256) && (ka >= 0) && (ka < Tseq);
                    bool ok1 = (d1 >= 0) && (d1 <= 256) && (ka+1 >= 0) && (ka+1 < Tseq);
                    float v0 = ok0 ? acc[mt][half][hr*2]   * scale : -1e30f;
                    float v1 = ok1 ? acc[mt][half][hr*2+1] * scale : -1e30f;
                    *(float2*)&S[qi*328 + kidx] = make_float2(v0, v1);
                }
    }
    __syncthreads();

    // ---- prefetch V block 0 (overlaps softmax) ----
    #pragma unroll
    for (int r = 0; r < 2; r++) {
        int kj = fi + r*32;
        int ka = qstart - 128 + kj;
        int kc = ka < 0 ? 0 : (ka >= Tseq ? Tseq-1 : ka);
        cp16z(sb + OFF_K0 + kj*144 + seg*16,
              q + (rowbase + kc)*1536 + 1024 + h*64 + seg*8,
              (ka >= 0 && ka < Tseq) ? 16 : 0);
    }
    cp_commit();

    // ---- softmax + P -> fp16 (1/sum folded) ----
    {
        __half* PH = (__half*)(smraw + OFF_P);
        for (int qq = wid*8; qq < wid*8 + 8; qq++) {
            float v[10]; float m = -1e30f;
            #pragma unroll
            for (int i = 0; i < 10; i++) { v[i] = S[qq*328 + lane + i*32]; m = fmaxf(m, v[i]); }
            #pragma unroll
            for (int o = 16; o > 0; o >>= 1) m = fmaxf(m, __shfl_xor_sync(0xffffffffu, m, o));
            float ssum = 0.f;
            #pragma unroll
            for (int i = 0; i < 10; i++) { v[i] = __expf(v[i] - m); ssum += v[i]; }
            #pragma unroll
            for (int o = 16; o > 0; o >>= 1) ssum += __shfl_xor_sync(0xffffffffu, ssum, o);
            float rs = 1.0f / ssum;
            #pragma unroll
            for (int i = 0; i < 10; i++)
                PH[qq*344 + lane + i*32] = __float2half(v[i] * rs);
        }
    }

    // ---- phase C: O = P V over 5 key blocks (double-buffered, trans ldsm) ----
    float oacc[2][2][4];
    #pragma unroll
    for (int i = 0; i < 2; i++)
        #pragma unroll
        for (int j = 0; j < 2; j++)
            #pragma unroll
            for (int r = 0; r < 4; r++) oacc[i][j][r] = 0.f;

    for (int kb = 0; kb < 5; kb++) {
        cp_wait<0>();
        __syncthreads();
        if (kb < 4) {
            uint32_t dstb = (kb + 1) & 1 ? OFF_K1 : OFF_K0;
            #pragma unroll
            for (int r = 0; r < 2; r++) {
                int kj = fi + r*32;
                int ka = qstart - 128 + (kb+1)*64 + kj;
                int kc = ka < 0 ? 0 : (ka >= Tseq ? Tseq-1 : ka);
                cp16z(sb + dstb + kj*144 + seg*16,
                      q + (rowbase + kc)*1536 + 1024 + h*64 + seg*8,
                      (ka >= 0 && ka < Tseq) ? 16 : 0);
            }
            cp_commit();
        }

        uint32_t vbuf = sb + (kb & 1 ? OFF_K1 : OFF_K0);
        #pragma unroll
        for (int ks = 0; ks < 4; ks++) {
            uint32_t aP[2][4];
            #pragma unroll
            for (int mt = 0; mt < 2; mt++)
                ldsm4(aP[mt], sb + OFF_P + (wm + mt*16 + a_row)*688 + (kb*64 + ks*16)*2 + a_koff);
            uint32_t bf[4];
            ldsm4t(bf, vbuf + (ks*16 + a_row)*144 + wn*2 + a_koff);
            #pragma unroll
            for (int mt = 0; mt < 2; mt++)
                #pragma unroll
                for (int half = 0; half < 2; half++)
                    mma16816(oacc[mt][half], aP[mt], &bf[half*2]);
        }
    }

    #pragma unroll
    for (int mt = 0; mt < 2; mt++)
        #pragma unroll
        for (int half = 0; half < 2; half++)
            #pragma unroll
            for (int hr = 0; hr < 2; hr++) {
                int qi = wm + mt*16 + (lane >> 2) + hr*8;
                int d  = wn + half*8 + (lane & 3)*2;
                size_t idx = (rowbase + qstart + qi)*512 + h*64 + d;
                *(__half2*)(outp + idx) =
                    __floats2half2_rn(oacc[mt][half][hr*2], oacc[mt][half][hr*2+1]);
            }
}

// ---------------- LayerNorm (+ optional fp16 output) -------------------------
__global__ __launch_bounds__(256)
void ln_kernel(const float* __restrict__ in, const float* __restrict__ gam,
               const float* __restrict__ bet, float* __restrict__ out,
               __half* __restrict__ oh)
{
    int row = blockIdx.x, tid = threadIdx.x;
    const float* p = in + (size_t)row * 512;
    float x0 = p[tid], x1 = p[tid + 256];
    float s = x0 + x1, q = x0*x0 + x1*x1;
    #pragma unroll
    for (int o = 16; o > 0; o >>= 1) {
        s += __shfl_xor_sync(0xffffffffu, s, o);
        q += __shfl_xor_sync(0xffffffffu, q, o);
    }
    __shared__ float ss[8], sq[8];
    int w = tid >> 5, l = tid & 31;
    if (l == 0) { ss[w] = s; sq[w] = q; }
    __syncthreads();
    float ts = 0.f, tq = 0.f;
    #pragma unroll
    for (int i = 0; i < 8; i++) { ts += ss[i]; tq += sq[i]; }
    float mean = ts * (1.0f/512.0f);
    float var  = tq * (1.0f/512.0f) - mean*mean;
    float inv  = rsqrtf(var + 1e-5f);
    float v0 = (x0 - mean) * inv * gam[tid]       + bet[tid];
    float v1 = (x1 - mean) * inv * gam[tid + 256] + bet[tid + 256];
    float* o = out + (size_t)row * 512;
    o[tid]       = v0;
    o[tid + 256] = v1;
    if (oh) {
        oh[(size_t)row*512 + tid]       = __float2half(v0);
        oh[(size_t)row*512 + tid + 256] = __float2half(v1);
    }
}

// ---------------- input projection ------------------------------------------
__global__ __launch_bounds__(128)
void inproj_kernel(const float* __restrict__ feat, const float* __restrict__ w,
                   const float* __restrict__ bias, const float* __restrict__ pe,
                   float* __restrict__ out, __half* __restrict__ oh)
{
    int row = blockIdx.x;
    int t = row & (Tseq - 1);
    __shared__ float f[32];
    if (threadIdx.x < 32) f[threadIdx.x] = feat[(size_t)row*32 + threadIdx.x];
    __syncthreads();
    int d0 = threadIdx.x * 4;
    float a[4];
    #pragma unroll
    for (int j = 0; j < 4; j++) a[j] = bias[d0 + j];
    #pragma unroll
    for (int j = 0; j < 4; j++) {
        const float4* wp = (const float4*)(w + (size_t)(d0 + j) * 32);
        #pragma unroll
        for (int k4 = 0; k4 < 8; k4++) {
            float4 wv = wp[k4];
            a[j] += wv.x*f[k4*4] + wv.y*f[k4*4+1] + wv.z*f[k4*4+2] + wv.w*f[k4*4+3];
        }
    }
    float4 pev = *(const float4*)(pe + (size_t)t*512 + d0);
    float4 r = make_float4(a[0]+pev.x, a[1]+pev.y, a[2]+pev.z, a[3]+pev.w);
    *(float4*)(out + (size_t)row*512 + d0) = r;
    *(__half2*)(oh + (size_t)row*512 + d0)     = __floats2half2_rn(r.x, r.y);
    *(__half2*)(oh + (size_t)row*512 + d0 + 2) = __floats2half2_rn(r.z, r.w);
}

// ---------------- launch ----------------------------------------------------
extern "C" void kernel_launch(void* const* d_in, const int* in_sizes, int n_in,
                              void* d_out, int out_size)
{
    const float* feat   = (const float*)d_in[0];
    const float* proj_w = (const float*)d_in[2];
    const float* proj_b = (const float*)d_in[3];
    const float* pe     = (const float*)d_in[4];
    const float* qkv_w  = (const float*)d_in[5];
    const float* qkv_b  = (const float*)d_in[6];
    const float* out_w  = (const float*)d_in[7];
    const float* out_b  = (const float*)d_in[8];
    const float* ff1_w  = (const float*)d_in[9];
    const float* ff1_b  = (const float*)d_in[10];
    const float* ff2_w  = (const float*)d_in[11];
    const float* ff2_b  = (const float*)d_in[12];
    const float* ln1_g  = (const float*)d_in[13];
    const float* ln1_b  = (const float*)d_in[14];
    const float* ln2_g  = (const float*)d_in[15];
    const float* ln2_b  = (const float*)d_in[16];

    float *x, *y;
    __half *q, *xa, *a, *f, *wq, *wo, *w1, *w2;
    cudaGetSymbolAddress((void**)&x,  g_x);
    cudaGetSymbolAddress((void**)&y,  g_y);
    cudaGetSymbolAddress((void**)&q,  g_q);
    cudaGetSymbolAddress((void**)&xa, g_xa);
    cudaGetSymbolAddress((void**)&a,  g_a);
    cudaGetSymbolAddress((void**)&f,  g_f);
    cudaGetSymbolAddress((void**)&wq, g_wq);
    cudaGetSymbolAddress((void**)&wo, g_wo);
    cudaGetSymbolAddress((void**)&w1, g_w1);
    cudaGetSymbolAddress((void**)&w2, g_w2);

    cudaFuncSetAttribute(attn_tc,    cudaFuncAttributeMaxDynamicSharedMemorySize, ATT_SMEM);
    cudaFuncSetAttribute(tc_gemm<0>, cudaFuncAttributeMaxDynamicSharedMemorySize, GS_TOTAL);
    cudaFuncSetAttribute(tc_gemm<1>, cudaFuncAttributeMaxDynamicSharedMemorySize, GS_TOTAL);
    cudaFuncSetAttribute(tc_gemm<2>, cudaFuncAttributeMaxDynamicSharedMemorySize, GS_TOTAL);
    cudaFuncSetAttribute(tc_gemm<3>, cudaFuncAttributeMaxDynamicSharedMemorySize, GS_TOTAL);

    {
        int n4;
        n4 = NLAYER*3*Dm*Dm/4; cvt4_kernel<<<(n4+255)/256,256>>>(qkv_w, wq, n4);
        n4 = NLAYER*Dm*Dm/4;   cvt4_kernel<<<(n4+255)/256,256>>>(out_w, wo, n4);
        n4 = NLAYER*FFd*Dm/4;  cvt4_kernel<<<(n4+255)/256,256>>>(ff1_w, w1, n4);
        n4 = NLAYER*Dm*FFd/4;  cvt4_kernel<<<(n4+255)/256,256>>>(ff2_w, w2, n4);
    }

    inproj_kernel<<<ROWS, 128>>>(feat, proj_w, proj_b, pe, x, xa);

    for (int l = 0; l < NLAYER; l++) {
        // QKV -> fp16
        tc_gemm<3><<<dim3(3*Dm/256, ROWS/128), 256, GS_TOTAL>>>(
            xa, wq + (size_t)l*3*Dm*Dm, qkv_b + (size_t)l*3*Dm, nullptr,
            nullptr, q, ROWS, 3*Dm, Dm);
        // banded attention -> a (fp16)
        attn_tc<<<dim3(Tseq/64, Hh, Bsz), 256, ATT_SMEM>>>(q, a);
        // out proj + residual(x) -> y
        tc_gemm<1><<<dim3(Dm/256, ROWS/128), 256, GS_TOTAL>>>(
            a, wo + (size_t)l*Dm*Dm, out_b + (size_t)l*Dm, x,
            y, nullptr, ROWS, Dm, Dm);
        ln_kernel<<<ROWS, 256>>>(y, ln1_g + (size_t)l*Dm, ln1_b + (size_t)l*Dm, x, xa);
        // FF1 + ReLU -> f (fp16)
        tc_gemm<2><<<dim3(FFd/256, ROWS/128), 256, GS_TOTAL>>>(
            xa, w1 + (size_t)l*FFd*Dm, ff1_b + (size_t)l*FFd, nullptr,
            nullptr, f, ROWS, FFd, Dm);
        // FF2 + residual(x) -> y
        tc_gemm<1><<<dim3(Dm/256, ROWS/128), 256, GS_TOTAL>>>(
            f, w2 + (size_t)l*Dm*FFd, ff2_b + (size_t)l*Dm, x,
            y, nullptr, ROWS, Dm, FFd);
        if (l == NLAYER - 1)
            ln_kernel<<<ROWS, 256>>>(y, ln2_g + (size_t)l*Dm, ln2_b + (size_t)l*Dm,
                                     (float*)d_out, nullptr);
        else
            ln_kernel<<<ROWS, 256>>>(y, ln2_g + (size_t)l*Dm, ln2_b + (size_t)l*Dm, x, xa);
    }
}

// round 10
// speedup vs baseline: 1.2226x; 1.0886x over previous
#include <cuda_runtime.h>
#include <cuda_fp16.h>
#include <cstdint>
#include <cstddef>

#define Bsz 4
#define Tseq 2048
#define Dm 512
#define Hh 8
#define FFd 2048
#define NLAYER 4
#define ROWS (Bsz*Tseq)   /* 8192 */

// ---------------- scratch (device globals; no allocations allowed) ----------
__device__ __align__(128) float g_x [ROWS*Dm];
__device__ __align__(128) float g_y [ROWS*Dm];
__device__ __align__(128) __half g_q [ROWS*3*Dm];
__device__ __align__(128) __half g_xa[ROWS*Dm];
__device__ __align__(128) __half g_a [ROWS*Dm];
__device__ __align__(128) __half g_f [ROWS*FFd];
__device__ __align__(128) __half g_wq[NLAYER*3*Dm*Dm];
__device__ __align__(128) __half g_wo[NLAYER*Dm*Dm];
__device__ __align__(128) __half g_w1[NLAYER*FFd*Dm];
__device__ __align__(128) __half g_w2[NLAYER*Dm*FFd];

// ---------------- helpers ----------------------------------------------------
__device__ __forceinline__ void cp16(uint32_t s, const void* g) {
    asm volatile("cp.async.cg.shared.global [%0], [%1], 16;" :: "r"(s), "l"(g));
}
__device__ __forceinline__ void cp16z(uint32_t s, const void* g, int sz) {
    asm volatile("cp.async.cg.shared.global [%0], [%1], 16, %2;" :: "r"(s), "l"(g), "r"(sz));
}
__device__ __forceinline__ void cp_commit() {
    asm volatile("cp.async.commit_group;" ::: "memory");
}
template<int N> __device__ __forceinline__ void cp_wait() {
    asm volatile("cp.async.wait_group %0;" :: "n"(N) : "memory");
}
__device__ __forceinline__ void ldsm4(uint32_t* r, uint32_t addr) {
    asm volatile("ldmatrix.sync.aligned.m8n8.x4.shared.b16 {%0,%1,%2,%3}, [%4];"
                 : "=r"(r[0]), "=r"(r[1]), "=r"(r[2]), "=r"(r[3]) : "r"(addr));
}
__device__ __forceinline__ void ldsm4t(uint32_t* r, uint32_t addr) {
    asm volatile("ldmatrix.sync.aligned.m8n8.x4.trans.shared.b16 {%0,%1,%2,%3}, [%4];"
                 : "=r"(r[0]), "=r"(r[1]), "=r"(r[2]), "=r"(r[3]) : "r"(addr));
}
__device__ __forceinline__ void mma16816(float* c, const uint32_t* a, const uint32_t* b) {
    asm volatile(
        "mma.sync.aligned.m16n8k16.row.col.f32.f16.f16.f32 "
        "{%0,%1,%2,%3}, {%4,%5,%6,%7}, {%8,%9}, {%0,%1,%2,%3};"
        : "+f"(c[0]), "+f"(c[1]), "+f"(c[2]), "+f"(c[3])
        : "r"(a[0]), "r"(a[1]), "r"(a[2]), "r"(a[3]), "r"(b[0]), "r"(b[1]));
}
__device__ __forceinline__ uint32_t packh2(float a, float b) {
    __half2 h = __floats2half2_rn(a, b);
    return *(uint32_t*)&h;
}

// ---------------- weight fp32 -> fp16 convert --------------------------------
__global__ __launch_bounds__(256)
void cvt4_kernel(const float* __restrict__ w, __half* __restrict__ h, int n4) {
    int i = blockIdx.x * 256 + threadIdx.x;
    if (i < n4) {
        float4 v = ((const float4*)w)[i];
        ((__half2*)h)[i*2]     = __floats2half2_rn(v.x, v.y);
        ((__half2*)h)[i*2 + 1] = __floats2half2_rn(v.z, v.w);
    }
}

// ---------------- HMMA GEMM: C[M,N] = A[M,K] @ W[N,K]^T ----------------------
// BM=128, BN=256, BK=32, 256 threads (8 warps, warp tile 64x64), 4-stage cp.async.
#define AROW 80
#define A_TILE (128*AROW)
#define B_TILE (256*AROW)
#define STAGE_B (A_TILE + B_TILE)
#define NSTAGE 4
#define GS_TOTAL (NSTAGE*STAGE_B)   /* 122880 */

__device__ __forceinline__ void gload(uint32_t st,
    const __half* __restrict__ A, const __half* __restrict__ B,
    int bm, int bn, int K, int k0, int tid)
{
    #pragma unroll
    for (int i = 0; i < 2; i++) {
        int idx = tid + i * 256;
        int row = idx >> 2, c = idx & 3;
        cp16(st + (uint32_t)(row * AROW + c * 16), A + (size_t)(bm + row) * K + k0 + c * 8);
    }
    #pragma unroll
    for (int i = 0; i < 4; i++) {
        int idx = tid + i * 256;
        int row = idx >> 2, c = idx & 3;
        cp16(st + A_TILE + (uint32_t)(row * AROW + c * 16), B + (size_t)(bn + row) * K + k0 + c * 8);
    }
    cp_commit();
}

template<int MODE>
__global__ __launch_bounds__(256, 1)
void tc_gemm(const __half* __restrict__ A, const __half* __restrict__ B,
             const float* __restrict__ bias, const float* __restrict__ res,
             float* __restrict__ Cf, __half* __restrict__ Ch,
             int M, int N, int K)
{
    extern __shared__ __align__(128) char smem[];
    uint32_t sb = (uint32_t)__cvta_generic_to_shared(smem);
    int tid = threadIdx.x;
    int wid = tid >> 5, lane = tid & 31;
    int bn = blockIdx.x * 256, bm = blockIdx.y * 128;
    int wm = (wid & 1) * 64;
    int wn = (wid >> 1) * 64;

    float acc[4][8][4];
    #pragma unroll
    for (int i = 0; i < 4; i++)
        #pragma unroll
        for (int j = 0; j < 8; j++)
            #pragma unroll
            for (int r = 0; r < 4; r++) acc[i][j][r] = 0.f;

    const int C = K >> 5;
    gload(sb,             A, B, bm, bn, K, 0,  tid);
    gload(sb +   STAGE_B, A, B, bm, bn, K, 32, tid);
    gload(sb + 2*STAGE_B, A, B, bm, bn, K, 64, tid);

    uint32_t a_row = (uint32_t)(lane & 15);
    uint32_t a_koff = (uint32_t)((lane >> 4) * 16);
    uint32_t b_row = (uint32_t)((lane & 7) + ((lane >> 4) << 3));
    uint32_t b_koff = (uint32_t)(((lane >> 3) & 1) * 16);

    for (int c = 0; c < C; c++) {
        if (c + 2 < C) cp_wait<2>();
        else if (c + 1 < C) cp_wait<1>();
        else cp_wait<0>();
        __syncthreads();
        if (c + 3 < C)
            gload(sb + ((c + 3) % NSTAGE) * STAGE_B, A, B, bm, bn, K, (c + 3) * 32, tid);

        uint32_t sa = sb + (c % NSTAGE) * STAGE_B;
        #pragma unroll
        for (int kk = 0; kk < 2; kk++) {
            uint32_t kb = (uint32_t)(kk * 32);
            uint32_t af[4][4];
            #pragma unroll
            for (int mt = 0; mt < 4; mt++)
                ldsm4(af[mt], sa + (wm + mt*16 + a_row) * AROW + kb + a_koff);
            #pragma unroll
            for (int ng = 0; ng < 4; ng++) {
                uint32_t bf[4];
                ldsm4(bf, sa + A_TILE + (wn + ng*16 + b_row) * AROW + kb + b_koff);
                #pragma unroll
                for (int mt = 0; mt < 4; mt++)
                    #pragma unroll
                    for (int half = 0; half < 2; half++)
                        mma16816(acc[mt][ng*2 + half], af[mt], &bf[half*2]);
            }
        }
    }

    #pragma unroll
    for (int mt = 0; mt < 4; mt++) {
        int m0 = bm + wm + mt*16 + (lane >> 2);
        #pragma unroll
        for (int nt = 0; nt < 8; nt++) {
            int n = bn + wn + nt*8 + (lane & 3)*2;
            float bx = bias[n], by = bias[n+1];
            #pragma unroll
            for (int h = 0; h < 2; h++) {
                int m = m0 + h*8;
                float v0 = acc[mt][nt][h*2]   + bx;
                float v1 = acc[mt][nt][h*2+1] + by;
                size_t idx = (size_t)m * N + n;
                if (MODE == 1) {
                    float2 rv = *(const float2*)&res[idx];
                    v0 += rv.x; v1 += rv.y;
                }
                if (MODE == 2 || MODE == 3) {
                    if (MODE == 2) { v0 = fmaxf(v0, 0.f); v1 = fmaxf(v1, 0.f); }
                    *(__half2*)(Ch + idx) = __floats2half2_rn(v0, v1);
                } else {
                    *(float2*)&Cf[idx] = make_float2(v0, v1);
                }
            }
        }
    }
}

// ---------------- flash banded attention (fp16, register softmax) ------------
// 128 threads (4 warps). Warp w owns query rows wm=w*16..+15 of the 64-query
// tile and the FULL 64-key width per block -> softmax reductions are
// quad-shuffles. S accumulator fragments are repacked in registers directly
// into PV A-fragments (no S/P SMEM at all). Online max/sum across 5 blocks.
#define OFF_Q  0
#define OFF_K0 9216
#define OFF_V0 18432
#define OFF_K1 27648
#define OFF_V1 36864
#define ATT_SMEM 46080

__global__ __launch_bounds__(128, 1)
void attn_flash(const __half* __restrict__ q, __half* __restrict__ outp)
{
    extern __shared__ __align__(128) char smraw[];
    uint32_t sb = (uint32_t)__cvta_generic_to_shared(smraw);

    int tid = threadIdx.x;
    int wid = tid >> 5, lane = tid & 31;
    int b = blockIdx.z, h = blockIdx.y;
    int qstart = blockIdx.x << 6;
    size_t rowbase = (size_t)b * Tseq;
    int wm = wid * 16;

    uint32_t a_row = (uint32_t)(lane & 15);
    uint32_t a_koff = (uint32_t)((lane >> 4) * 16);
    uint32_t b_row = (uint32_t)((lane & 7) + ((lane >> 4) << 3));
    uint32_t b_koff = (uint32_t)(((lane >> 3) & 1) * 16);

    int fi = tid >> 3;       // 0..15
    int seg = tid & 7;

    // ---- group 0: Q tile + K0 + V0 ----
    #pragma unroll
    for (int r = 0; r < 4; r++) {
        int qi = fi + r*16;
        cp16(sb + OFF_Q + qi*144 + seg*16,
             q + (rowbase + qstart + qi)*1536 + h*64 + seg*8);
    }
    #pragma unroll
    for (int r = 0; r < 4; r++) {
        int kj = fi + r*16;
        int ka = qstart - 128 + kj;
        int kc = ka < 0 ? 0 : (ka >= Tseq ? Tseq-1 : ka);
        int ok = (ka >= 0 && ka < Tseq) ? 16 : 0;
        cp16z(sb + OFF_K0 + kj*144 + seg*16,
              q + (rowbase + kc)*1536 + 512 + h*64 + seg*8, ok);
        cp16z(sb + OFF_V0 + kj*144 + seg*16,
              q + (rowbase + kc)*1536 + 1024 + h*64 + seg*8, ok);
    }
    cp_commit();

    const float scale = 0.125f;
    uint32_t af[4][4];
    float m_run[2] = {-1e30f, -1e30f};
    float l_run[2] = {0.f, 0.f};
    float oacc[8][4];
    #pragma unroll
    for (int nt = 0; nt < 8; nt++)
        #pragma unroll
        for (int r = 0; r < 4; r++) oacc[nt][r] = 0.f;

    for (int kb = 0; kb < 5; kb++) {
        cp_wait<0>();
        __syncthreads();
        if (kb == 0) {
            #pragma unroll
            for (int ks = 0; ks < 4; ks++)
                ldsm4(af[ks], sb + OFF_Q + (wm + a_row)*144 + ks*32 + a_koff);
        }
        if (kb < 4) {
            uint32_t kd = (kb + 1) & 1 ? OFF_K1 : OFF_K0;
            uint32_t vd = (kb + 1) & 1 ? OFF_V1 : OFF_V0;
            #pragma unroll
            for (int r = 0; r < 4; r++) {
                int kj = fi + r*16;
                int ka = qstart - 128 + (kb+1)*64 + kj;
                int kc = ka < 0 ? 0 : (ka >= Tseq ? Tseq-1 : ka);
                int ok = (ka >= 0 && ka < Tseq) ? 16 : 0;
                cp16z(sb + kd + kj*144 + seg*16,
                      q + (rowbase + kc)*1536 + 512 + h*64 + seg*8, ok);
                cp16z(sb + vd + kj*144 + seg*16,
                      q + (rowbase + kc)*1536 + 1024 + h*64 + seg*8, ok);
            }
            cp_commit();
        }

        uint32_t kbuf = sb + (kb & 1 ? OFF_K1 : OFF_K0);
        uint32_t vbuf = sb + (kb & 1 ? OFF_V1 : OFF_V0);

        // ---- S = Q K^T (m16 x n64) ----
        float sacc[8][4];
        #pragma unroll
        for (int nt = 0; nt < 8; nt++)
            #pragma unroll
            for (int r = 0; r < 4; r++) sacc[nt][r] = 0.f;

        #pragma unroll
        for (int ks = 0; ks < 4; ks++) {
            #pragma unroll
            for (int ng = 0; ng < 4; ng++) {
                uint32_t bf[4];
                ldsm4(bf, kbuf + (ng*16 + b_row)*144 + ks*32 + b_koff);
                mma16816(sacc[ng*2],     af[ks], bf);
                mma16816(sacc[ng*2 + 1], af[ks], &bf[2]);
            }
        }

        // ---- mask + scale ----
        #pragma unroll
        for (int nt = 0; nt < 8; nt++)
            #pragma unroll
            for (int r = 0; r < 4; r++) {
                int qi   = wm + (lane >> 2) + (r >> 1)*8;
                int kidx = kb*64 + nt*8 + (lane & 3)*2 + (r & 1);
                int ka   = qstart - 128 + kidx;
                int delta = kidx - qi;
                bool ok = (delta >= 0) && (delta <= 256) && (ka >= 0) && (ka < Tseq);
                sacc[nt][r] = ok ? sacc[nt][r] * scale : -1e30f;
            }

        // ---- online softmax (per row-half hr) ----
        #pragma unroll
        for (int hr = 0; hr < 2; hr++) {
            float mb = -1e30f;
            #pragma unroll
            for (int nt = 0; nt < 8; nt++) {
                mb = fmaxf(mb, sacc[nt][hr*2]);
                mb = fmaxf(mb, sacc[nt][hr*2 + 1]);
            }
            mb = fmaxf(mb, __shfl_xor_sync(0xffffffffu, mb, 1));
            mb = fmaxf(mb, __shfl_xor_sync(0xffffffffu, mb, 2));
            float m_new = fmaxf(m_run[hr], mb);
            float factor = __expf(m_run[hr] - m_new);
            float psum = 0.f;
            #pragma unroll
            for (int nt = 0; nt < 8; nt++)
                #pragma unroll
                for (int j = 0; j < 2; j++) {
                    float s = sacc[nt][hr*2 + j];
                    float p = (s > -1e29f) ? __expf(s - m_new) : 0.f;
                    sacc[nt][hr*2 + j] = p;
                    psum += p;
                }
            psum += __shfl_xor_sync(0xffffffffu, psum, 1);
            psum += __shfl_xor_sync(0xffffffffu, psum, 2);
            l_run[hr] = l_run[hr] * factor + psum;
            m_run[hr] = m_new;
            #pragma unroll
            for (int nt = 0; nt < 8; nt++)
                #pragma unroll
                for (int j = 0; j < 2; j++)
                    oacc[nt][hr*2 + j] *= factor;
        }

        // ---- pack P into PV A-fragments (register-only) ----
        uint32_t pf[4][4];
        #pragma unroll
        for (int ks = 0; ks < 4; ks++) {
            pf[ks][0] = packh2(sacc[2*ks][0],     sacc[2*ks][1]);
            pf[ks][1] = packh2(sacc[2*ks][2],     sacc[2*ks][3]);
            pf[ks][2] = packh2(sacc[2*ks + 1][0], sacc[2*ks + 1][1]);
            pf[ks][3] = packh2(sacc[2*ks + 1][2], sacc[2*ks + 1][3]);
        }

        // ---- O += P V (m16 x n64, k64; V via trans ldsm) ----
        #pragma unroll
        for (int ks = 0; ks < 4; ks++) {
            #pragma unroll
            for (int dn = 0; dn < 4; dn++) {
                uint32_t bf[4];
                ldsm4t(bf, vbuf + (ks*16 + a_row)*144 + dn*32 + a_koff);
                mma16816(oacc[dn*2],     pf[ks], bf);
                mma16816(oacc[dn*2 + 1], pf[ks], &bf[2]);
            }
        }
    }

    // ---- epilogue: normalize by 1/l and store ----
    #pragma unroll
    for (int hr = 0; hr < 2; hr++) {
        float rs = 1.0f / l_run[hr];
        int qi = qstart + wm + (lane >> 2) + hr*8;
        #pragma unroll
        for (int nt = 0; nt < 8; nt++) {
            int d = nt*8 + (lane & 3)*2;
            size_t idx = (rowbase + qi)*512 + h*64 + d;
            *(__half2*)(outp + idx) =
                __floats2half2_rn(oacc[nt][hr*2] * rs, oacc[nt][hr*2 + 1] * rs);
        }
    }
}

// ---------------- LayerNorm (+ optional fp16 output) -------------------------
__global__ __launch_bounds__(256)
void ln_kernel(const float* __restrict__ in, const float* __restrict__ gam,
               const float* __restrict__ bet, float* __restrict__ out,
               __half* __restrict__ oh)
{
    int row = blockIdx.x, tid = threadIdx.x;
    const float* p = in + (size_t)row * 512;
    float x0 = p[tid], x1 = p[tid + 256];
    float s = x0 + x1, q = x0*x0 + x1*x1;
    #pragma unroll
    for (int o = 16; o > 0; o >>= 1) {
        s += __shfl_xor_sync(0xffffffffu, s, o);
        q += __shfl_xor_sync(0xffffffffu, q, o);
    }
    __shared__ float ss[8], sq[8];
    int w = tid >> 5, l = tid & 31;
    if (l == 0) { ss[w] = s; sq[w] = q; }
    __syncthreads();
    float ts = 0.f, tq = 0.f;
    #pragma unroll
    for (int i = 0; i < 8; i++) { ts += ss[i]; tq += sq[i]; }
    float mean = ts * (1.0f/512.0f);
    float var  = tq * (1.0f/512.0f) - mean*mean;
    float inv  = rsqrtf(var + 1e-5f);
    float v0 = (x0 - mean) * inv * gam[tid]       + bet[tid];
    float v1 = (x1 - mean) * inv * gam[tid + 256] + bet[tid + 256];
    float* o = out + (size_t)row * 512;
    o[tid]       = v0;
    o[tid + 256] = v1;
    if (oh) {
        oh[(size_t)row*512 + tid]       = __float2half(v0);
        oh[(size_t)row*512 + tid + 256] = __float2half(v1);
    }
}

// ---------------- input projection ------------------------------------------
__global__ __launch_bounds__(128)
void inproj_kernel(const float* __restrict__ feat, const float* __restrict__ w,
                   const float* __restrict__ bias, const float* __restrict__ pe,
                   float* __restrict__ out, __half* __restrict__ oh)
{
    int row = blockIdx.x;
    int t = row & (Tseq - 1);
    __shared__ float f[32];
    if (threadIdx.x < 32) f[threadIdx.x] = feat[(size_t)row*32 + threadIdx.x];
    __syncthreads();
    int d0 = threadIdx.x * 4;
    float a[4];
    #pragma unroll
    for (int j = 0; j < 4; j++) a[j] = bias[d0 + j];
    #pragma unroll
    for (int j = 0; j < 4; j++) {
        const float4* wp = (const float4*)(w + (size_t)(d0 + j) * 32);
        #pragma unroll
        for (int k4 = 0; k4 < 8; k4++) {
            float4 wv = wp[k4];
            a[j] += wv.x*f[k4*4] + wv.y*f[k4*4+1] + wv.z*f[k4*4+2] + wv.w*f[k4*4+3];
        }
    }
    float4 pev = *(const float4*)(pe + (size_t)t*512 + d0);
    float4 r = make_float4(a[0]+pev.x, a[1]+pev.y, a[2]+pev.z, a[3]+pev.w);
    *(float4*)(out + (size_t)row*512 + d0) = r;
    *(__half2*)(oh + (size_t)row*512 + d0)     = __floats2half2_rn(r.x, r.y);
    *(__half2*)(oh + (size_t)row*512 + d0 + 2) = __floats2half2_rn(r.z, r.w);
}

// ---------------- launch ----------------------------------------------------
extern "C" void kernel_launch(void* const* d_in, const int* in_sizes, int n_in,
                              void* d_out, int out_size)
{
    const float* feat   = (const float*)d_in[0];
    const float* proj_w = (const float*)d_in[2];
    const float* proj_b = (const float*)d_in[3];
    const float* pe     = (const float*)d_in[4];
    const float* qkv_w  = (const float*)d_in[5];
    const float* qkv_b  = (const float*)d_in[6];
    const float* out_w  = (const float*)d_in[7];
    const float* out_b  = (const float*)d_in[8];
    const float* ff1_w  = (const float*)d_in[9];
    const float* ff1_b  = (const float*)d_in[10];
    const float* ff2_w  = (const float*)d_in[11];
    const float* ff2_b  = (const float*)d_in[12];
    const float* ln1_g  = (const float*)d_in[13];
    const float* ln1_b  = (const float*)d_in[14];
    const float* ln2_g  = (const float*)d_in[15];
    const float* ln2_b  = (const float*)d_in[16];

    float *x, *y;
    __half *q, *xa, *a, *f, *wq, *wo, *w1, *w2;
    cudaGetSymbolAddress((void**)&x,  g_x);
    cudaGetSymbolAddress((void**)&y,  g_y);
    cudaGetSymbolAddress((void**)&q,  g_q);
    cudaGetSymbolAddress((void**)&xa, g_xa);
    cudaGetSymbolAddress((void**)&a,  g_a);
    cudaGetSymbolAddress((void**)&f,  g_f);
    cudaGetSymbolAddress((void**)&wq, g_wq);
    cudaGetSymbolAddress((void**)&wo, g_wo);
    cudaGetSymbolAddress((void**)&w1, g_w1);
    cudaGetSymbolAddress((void**)&w2, g_w2);

    cudaFuncSetAttribute(attn_flash, cudaFuncAttributeMaxDynamicSharedMemorySize, ATT_SMEM);
    cudaFuncSetAttribute(tc_gemm<0>, cudaFuncAttributeMaxDynamicSharedMemorySize, GS_TOTAL);
    cudaFuncSetAttribute(tc_gemm<1>, cudaFuncAttributeMaxDynamicSharedMemorySize, GS_TOTAL);
    cudaFuncSetAttribute(tc_gemm<2>, cudaFuncAttributeMaxDynamicSharedMemorySize, GS_TOTAL);
    cudaFuncSetAttribute(tc_gemm<3>, cudaFuncAttributeMaxDynamicSharedMemorySize, GS_TOTAL);

    {
        int n4;
        n4 = NLAYER*3*Dm*Dm/4; cvt4_kernel<<<(n4+255)/256,256>>>(qkv_w, wq, n4);
        n4 = NLAYER*Dm*Dm/4;   cvt4_kernel<<<(n4+255)/256,256>>>(out_w, wo, n4);
        n4 = NLAYER*FFd*Dm/4;  cvt4_kernel<<<(n4+255)/256,256>>>(ff1_w, w1, n4);
        n4 = NLAYER*Dm*FFd/4;  cvt4_kernel<<<(n4+255)/256,256>>>(ff2_w, w2, n4);
    }

    inproj_kernel<<<ROWS, 128>>>(feat, proj_w, proj_b, pe, x, xa);

    for (int l = 0; l < NLAYER; l++) {
        // QKV -> fp16
        tc_gemm<3><<<dim3(3*Dm/256, ROWS/128), 256, GS_TOTAL>>>(
            xa, wq + (size_t)l*3*Dm*Dm, qkv_b + (size_t)l*3*Dm, nullptr,
            nullptr, q, ROWS, 3*Dm, Dm);
        // flash banded attention -> a (fp16)
        attn_flash<<<dim3(Tseq/64, Hh, Bsz), 128, ATT_SMEM>>>(q, a);
        // out proj + residual(x) -> y
        tc_gemm<1><<<dim3(Dm/256, ROWS/128), 256, GS_TOTAL>>>(
            a, wo + (size_t)l*Dm*Dm, out_b + (size_t)l*Dm, x,
            y, nullptr, ROWS, Dm, Dm);
        ln_kernel<<<ROWS, 256>>>(y, ln1_g + (size_t)l*Dm, ln1_b + (size_t)l*Dm, x, xa);
        // FF1 + ReLU -> f (fp16)
        tc_gemm<2><<<dim3(FFd/256, ROWS/128), 256, GS_TOTAL>>>(
            xa, w1 + (size_t)l*FFd*Dm, ff1_b + (size_t)l*FFd, nullptr,
            nullptr, f, ROWS, FFd, Dm);
        // FF2 + residual(x) -> y
        tc_gemm<1><<<dim3(Dm/256, ROWS/128), 256, GS_TOTAL>>>(
            f, w2 + (size_t)l*Dm*FFd, ff2_b + (size_t)l*Dm, x,
            y, nullptr, ROWS, Dm, FFd);
        if (l == NLAYER - 1)
            ln_kernel<<<ROWS, 256>>>(y, ln2_g + (size_t)l*Dm, ln2_b + (size_t)l*Dm,
                                     (float*)d_out, nullptr);
        else
            ln_kernel<<<ROWS, 256>>>(y, ln2_g + (size_t)l*Dm, ln2_b + (size_t)l*Dm, x, xa);
    }
}

// round 11
// speedup vs baseline: 1.3928x; 1.1392x over previous
#include <cuda_runtime.h>
#include <cuda_fp16.h>
#include <cstdint>
#include <cstddef>

#define Bsz 4
#define Tseq 2048
#define Dm 512
#define Hh 8
#define FFd 2048
#define NLAYER 4
#define ROWS (Bsz*Tseq)   /* 8192 */

// ---------------- scratch (device globals; no allocations allowed) ----------
__device__ __align__(128) float g_x [ROWS*Dm];
__device__ __align__(128) float g_y [ROWS*Dm];
__device__ __align__(128) __half g_q [ROWS*3*Dm];
__device__ __align__(128) __half g_xa[ROWS*Dm];
__device__ __align__(128) __half g_a [ROWS*Dm];
__device__ __align__(128) __half g_f [ROWS*FFd];
__device__ __align__(128) __half g_wq[NLAYER*3*Dm*Dm];
__device__ __align__(128) __half g_wo[NLAYER*Dm*Dm];
__device__ __align__(128) __half g_w1[NLAYER*FFd*Dm];
__device__ __align__(128) __half g_w2[NLAYER*Dm*FFd];

// ---------------- helpers ----------------------------------------------------
__device__ __forceinline__ void cp16(uint32_t s, const void* g) {
    asm volatile("cp.async.cg.shared.global [%0], [%1], 16;" :: "r"(s), "l"(g));
}
__device__ __forceinline__ void cp16z(uint32_t s, const void* g, int sz) {
    asm volatile("cp.async.cg.shared.global [%0], [%1], 16, %2;" :: "r"(s), "l"(g), "r"(sz));
}
__device__ __forceinline__ void cp_commit() {
    asm volatile("cp.async.commit_group;" ::: "memory");
}
template<int N> __device__ __forceinline__ void cp_wait() {
    asm volatile("cp.async.wait_group %0;" :: "n"(N) : "memory");
}
__device__ __forceinline__ void ldsm4(uint32_t* r, uint32_t addr) {
    asm volatile("ldmatrix.sync.aligned.m8n8.x4.shared.b16 {%0,%1,%2,%3}, [%4];"
                 : "=r"(r[0]), "=r"(r[1]), "=r"(r[2]), "=r"(r[3]) : "r"(addr));
}
__device__ __forceinline__ void ldsm4t(uint32_t* r, uint32_t addr) {
    asm volatile("ldmatrix.sync.aligned.m8n8.x4.trans.shared.b16 {%0,%1,%2,%3}, [%4];"
                 : "=r"(r[0]), "=r"(r[1]), "=r"(r[2]), "=r"(r[3]) : "r"(addr));
}
__device__ __forceinline__ void mma16816(float* c, const uint32_t* a, const uint32_t* b) {
    asm volatile(
        "mma.sync.aligned.m16n8k16.row.col.f32.f16.f16.f32 "
        "{%0,%1,%2,%3}, {%4,%5,%6,%7}, {%8,%9}, {%0,%1,%2,%3};"
        : "+f"(c[0]), "+f"(c[1]), "+f"(c[2]), "+f"(c[3])
        : "r"(a[0]), "r"(a[1]), "r"(a[2]), "r"(a[3]), "r"(b[0]), "r"(b[1]));
}
__device__ __forceinline__ uint32_t packh2(float a, float b) {
    __half2 h = __floats2half2_rn(a, b);
    return *(uint32_t*)&h;
}

// ---------------- weight fp32 -> fp16 convert --------------------------------
__global__ __launch_bounds__(256)
void cvt4_kernel(const float* __restrict__ w, __half* __restrict__ h, int n4) {
    int i = blockIdx.x * 256 + threadIdx.x;
    if (i < n4) {
        float4 v = ((const float4*)w)[i];
        ((__half2*)h)[i*2]     = __floats2half2_rn(v.x, v.y);
        ((__half2*)h)[i*2 + 1] = __floats2half2_rn(v.z, v.w);
    }
}

// ---------------- HMMA GEMM: C[M,N] = A[M,K] @ W[N,K]^T ----------------------
// BM=128, BN=128, BK=32, 128 threads (4 warps, warp tile 64x64), 4-stage
// cp.async, 2 CTAs/SM for bubble-filling.
#define AROW 80
#define A_TILE (128*AROW)            /* 10240 */
#define B_TILE (128*AROW)            /* 10240 */
#define STAGE_B (A_TILE + B_TILE)    /* 20480 */
#define NSTAGE 4
#define GS_TOTAL (NSTAGE*STAGE_B)    /* 81920 per CTA */

__device__ __forceinline__ void gload(uint32_t st,
    const __half* __restrict__ A, const __half* __restrict__ B,
    int bm, int bn, int K, int k0, int tid)
{
    #pragma unroll
    for (int i = 0; i < 4; i++) {
        int idx = tid + i * 128;
        int row = idx >> 2, c = idx & 3;
        cp16(st + (uint32_t)(row * AROW + c * 16), A + (size_t)(bm + row) * K + k0 + c * 8);
    }
    #pragma unroll
    for (int i = 0; i < 4; i++) {
        int idx = tid + i * 128;
        int row = idx >> 2, c = idx & 3;
        cp16(st + A_TILE + (uint32_t)(row * AROW + c * 16), B + (size_t)(bn + row) * K + k0 + c * 8);
    }
    cp_commit();
}

template<int MODE>
__global__ __launch_bounds__(128, 2)
void tc_gemm(const __half* __restrict__ A, const __half* __restrict__ B,
             const float* __restrict__ bias, const float* __restrict__ res,
             float* __restrict__ Cf, __half* __restrict__ Ch,
             int M, int N, int K)
{
    extern __shared__ __align__(128) char smem[];
    uint32_t sb = (uint32_t)__cvta_generic_to_shared(smem);
    int tid = threadIdx.x;
    int wid = tid >> 5, lane = tid & 31;
    int bn = blockIdx.x * 128, bm = blockIdx.y * 128;
    int wm = (wid & 1) * 64;
    int wn = (wid >> 1) * 64;

    float acc[4][8][4];
    #pragma unroll
    for (int i = 0; i < 4; i++)
        #pragma unroll
        for (int j = 0; j < 8; j++)
            #pragma unroll
            for (int r = 0; r < 4; r++) acc[i][j][r] = 0.f;

    const int C = K >> 5;
    gload(sb,             A, B, bm, bn, K, 0,  tid);
    gload(sb +   STAGE_B, A, B, bm, bn, K, 32, tid);
    gload(sb + 2*STAGE_B, A, B, bm, bn, K, 64, tid);

    uint32_t a_row = (uint32_t)(lane & 15);
    uint32_t a_koff = (uint32_t)((lane >> 4) * 16);
    uint32_t b_row = (uint32_t)((lane & 7) + ((lane >> 4) << 3));
    uint32_t b_koff = (uint32_t)(((lane >> 3) & 1) * 16);

    for (int c = 0; c < C; c++) {
        if (c + 2 < C) cp_wait<2>();
        else if (c + 1 < C) cp_wait<1>();
        else cp_wait<0>();
        __syncthreads();
        if (c + 3 < C)
            gload(sb + ((c + 3) % NSTAGE) * STAGE_B, A, B, bm, bn, K, (c + 3) * 32, tid);

        uint32_t sa = sb + (c % NSTAGE) * STAGE_B;
        #pragma unroll
        for (int kk = 0; kk < 2; kk++) {
            uint32_t kb = (uint32_t)(kk * 32);
            uint32_t af[4][4];
            #pragma unroll
            for (int mt = 0; mt < 4; mt++)
                ldsm4(af[mt], sa + (wm + mt*16 + a_row) * AROW + kb + a_koff);
            #pragma unroll
            for (int ng = 0; ng < 4; ng++) {
                uint32_t bf[4];
                ldsm4(bf, sa + A_TILE + (wn + ng*16 + b_row) * AROW + kb + b_koff);
                #pragma unroll
                for (int mt = 0; mt < 4; mt++)
                    #pragma unroll
                    for (int half = 0; half < 2; half++)
                        mma16816(acc[mt][ng*2 + half], af[mt], &bf[half*2]);
            }
        }
    }

    #pragma unroll
    for (int mt = 0; mt < 4; mt++) {
        int m0 = bm + wm + mt*16 + (lane >> 2);
        #pragma unroll
        for (int nt = 0; nt < 8; nt++) {
            int n = bn + wn + nt*8 + (lane & 3)*2;
            float bx = bias[n], by = bias[n+1];
            #pragma unroll
            for (int h = 0; h < 2; h++) {
                int m = m0 + h*8;
                float v0 = acc[mt][nt][h*2]   + bx;
                float v1 = acc[mt][nt][h*2+1] + by;
                size_t idx = (size_t)m * N + n;
                if (MODE == 1) {
                    float2 rv = *(const float2*)&res[idx];
                    v0 += rv.x; v1 += rv.y;
                }
                if (MODE == 2 || MODE == 3) {
                    if (MODE == 2) { v0 = fmaxf(v0, 0.f); v1 = fmaxf(v1, 0.f); }
                    *(__half2*)(Ch + idx) = __floats2half2_rn(v0, v1);
                } else {
                    *(float2*)&Cf[idx] = make_float2(v0, v1);
                }
            }
        }
    }
}

// ---------------- flash banded attention (fp16, register softmax) ------------
#define OFF_Q  0
#define OFF_K0 9216
#define OFF_V0 18432
#define OFF_K1 27648
#define OFF_V1 36864
#define ATT_SMEM 46080

__global__ __launch_bounds__(128, 1)
void attn_flash(const __half* __restrict__ q, __half* __restrict__ outp)
{
    extern __shared__ __align__(128) char smraw[];
    uint32_t sb = (uint32_t)__cvta_generic_to_shared(smraw);

    int tid = threadIdx.x;
    int wid = tid >> 5, lane = tid & 31;
    int b = blockIdx.z, h = blockIdx.y;
    int qstart = blockIdx.x << 6;
    size_t rowbase = (size_t)b * Tseq;
    int wm = wid * 16;

    uint32_t a_row = (uint32_t)(lane & 15);
    uint32_t a_koff = (uint32_t)((lane >> 4) * 16);
    uint32_t b_row = (uint32_t)((lane & 7) + ((lane >> 4) << 3));
    uint32_t b_koff = (uint32_t)(((lane >> 3) & 1) * 16);

    int fi = tid >> 3;
    int seg = tid & 7;

    #pragma unroll
    for (int r = 0; r < 4; r++) {
        int qi = fi + r*16;
        cp16(sb + OFF_Q + qi*144 + seg*16,
             q + (rowbase + qstart + qi)*1536 + h*64 + seg*8);
    }
    #pragma unroll
    for (int r = 0; r < 4; r++) {
        int kj = fi + r*16;
        int ka = qstart - 128 + kj;
        int kc = ka < 0 ? 0 : (ka >= Tseq ? Tseq-1 : ka);
        int ok = (ka >= 0 && ka < Tseq) ? 16 : 0;
        cp16z(sb + OFF_K0 + kj*144 + seg*16,
              q + (rowbase + kc)*1536 + 512 + h*64 + seg*8, ok);
        cp16z(sb + OFF_V0 + kj*144 + seg*16,
              q + (rowbase + kc)*1536 + 1024 + h*64 + seg*8, ok);
    }
    cp_commit();

    const float scale = 0.125f;
    uint32_t af[4][4];
    float m_run[2] = {-1e30f, -1e30f};
    float l_run[2] = {0.f, 0.f};
    float oacc[8][4];
    #pragma unroll
    for (int nt = 0; nt < 8; nt++)
        #pragma unroll
        for (int r = 0; r < 4; r++) oacc[nt][r] = 0.f;

    for (int kb = 0; kb < 5; kb++) {
        cp_wait<0>();
        __syncthreads();
        if (kb == 0) {
            #pragma unroll
            for (int ks = 0; ks < 4; ks++)
                ldsm4(af[ks], sb + OFF_Q + (wm + a_row)*144 + ks*32 + a_koff);
        }
        if (kb < 4) {
            uint32_t kd = (kb + 1) & 1 ? OFF_K1 : OFF_K0;
            uint32_t vd = (kb + 1) & 1 ? OFF_V1 : OFF_V0;
            #pragma unroll
            for (int r = 0; r < 4; r++) {
                int kj = fi + r*16;
                int ka = qstart - 128 + (kb+1)*64 + kj;
                int kc = ka < 0 ? 0 : (ka >= Tseq ? Tseq-1 : ka);
                int ok = (ka >= 0 && ka < Tseq) ? 16 : 0;
                cp16z(sb + kd + kj*144 + seg*16,
                      q + (rowbase + kc)*1536 + 512 + h*64 + seg*8, ok);
                cp16z(sb + vd + kj*144 + seg*16,
                      q + (rowbase + kc)*1536 + 1024 + h*64 + seg*8, ok);
            }
            cp_commit();
        }

        uint32_t kbuf = sb + (kb & 1 ? OFF_K1 : OFF_K0);
        uint32_t vbuf = sb + (kb & 1 ? OFF_V1 : OFF_V0);

        float sacc[8][4];
        #pragma unroll
        for (int nt = 0; nt < 8; nt++)
            #pragma unroll
            for (int r = 0; r < 4; r++) sacc[nt][r] = 0.f;

        #pragma unroll
        for (int ks = 0; ks < 4; ks++) {
            #pragma unroll
            for (int ng = 0; ng < 4; ng++) {
                uint32_t bf[4];
                ldsm4(bf, kbuf + (ng*16 + b_row)*144 + ks*32 + b_koff);
                mma16816(sacc[ng*2],     af[ks], bf);
                mma16816(sacc[ng*2 + 1], af[ks], &bf[2]);
            }
        }

        #pragma unroll
        for (int nt = 0; nt < 8; nt++)
            #pragma unroll
            for (int r = 0; r < 4; r++) {
                int qi   = wm + (lane >> 2) + (r >> 1)*8;
                int kidx = kb*64 + nt*8 + (lane & 3)*2 + (r & 1);
                int ka   = qstart - 128 + kidx;
                int delta = kidx - qi;
                bool ok = (delta >= 0) && (delta <= 256) && (ka >= 0) && (ka < Tseq);
                sacc[nt][r] = ok ? sacc[nt][r] * scale : -1e30f;
            }

        #pragma unroll
        for (int hr = 0; hr < 2; hr++) {
            float mb = -1e30f;
            #pragma unroll
            for (int nt = 0; nt < 8; nt++) {
                mb = fmaxf(mb, sacc[nt][hr*2]);
                mb = fmaxf(mb, sacc[nt][hr*2 + 1]);
            }
            mb = fmaxf(mb, __shfl_xor_sync(0xffffffffu, mb, 1));
            mb = fmaxf(mb, __shfl_xor_sync(0xffffffffu, mb, 2));
            float m_new = fmaxf(m_run[hr], mb);
            float factor = __expf(m_run[hr] - m_new);
            float psum = 0.f;
            #pragma unroll
            for (int nt = 0; nt < 8; nt++)
                #pragma unroll
                for (int j = 0; j < 2; j++) {
                    float s = sacc[nt][hr*2 + j];
                    float p = (s > -1e29f) ? __expf(s - m_new) : 0.f;
                    sacc[nt][hr*2 + j] = p;
                    psum += p;
                }
            psum += __shfl_xor_sync(0xffffffffu, psum, 1);
            psum += __shfl_xor_sync(0xffffffffu, psum, 2);
            l_run[hr] = l_run[hr] * factor + psum;
            m_run[hr] = m_new;
            #pragma unroll
            for (int nt = 0; nt < 8; nt++)
                #pragma unroll
                for (int j = 0; j < 2; j++)
                    oacc[nt][hr*2 + j] *= factor;
        }

        uint32_t pf[4][4];
        #pragma unroll
        for (int ks = 0; ks < 4; ks++) {
            pf[ks][0] = packh2(sacc[2*ks][0],     sacc[2*ks][1]);
            pf[ks][1] = packh2(sacc[2*ks][2],     sacc[2*ks][3]);
            pf[ks][2] = packh2(sacc[2*ks + 1][0], sacc[2*ks + 1][1]);
            pf[ks][3] = packh2(sacc[2*ks + 1][2], sacc[2*ks + 1][3]);
        }

        #pragma unroll
        for (int ks = 0; ks < 4; ks++) {
            #pragma unroll
            for (int dn = 0; dn < 4; dn++) {
                uint32_t bf[4];
                ldsm4t(bf, vbuf + (ks*16 + a_row)*144 + dn*32 + a_koff);
                mma16816(oacc[dn*2],     pf[ks], bf);
                mma16816(oacc[dn*2 + 1], pf[ks], &bf[2]);
            }
        }
    }

    #pragma unroll
    for (int hr = 0; hr < 2; hr++) {
        float rs = 1.0f / l_run[hr];
        int qi = qstart + wm + (lane >> 2) + hr*8;
        #pragma unroll
        for (int nt = 0; nt < 8; nt++) {
            int d = nt*8 + (lane & 3)*2;
            size_t idx = (rowbase + qi)*512 + h*64 + d;
            *(__half2*)(outp + idx) =
                __floats2half2_rn(oacc[nt][hr*2] * rs, oacc[nt][hr*2 + 1] * rs);
        }
    }
}

// ---------------- LayerNorm (+ optional fp16 output) -------------------------
__global__ __launch_bounds__(256)
void ln_kernel(const float* __restrict__ in, const float* __restrict__ gam,
               const float* __restrict__ bet, float* __restrict__ out,
               __half* __restrict__ oh)
{
    int row = blockIdx.x, tid = threadIdx.x;
    const float* p = in + (size_t)row * 512;
    float x0 = p[tid], x1 = p[tid + 256];
    float s = x0 + x1, q = x0*x0 + x1*x1;
    #pragma unroll
    for (int o = 16; o > 0; o >>= 1) {
        s += __shfl_xor_sync(0xffffffffu, s, o);
        q += __shfl_xor_sync(0xffffffffu, q, o);
    }
    __shared__ float ss[8], sq[8];
    int w = tid >> 5, l = tid & 31;
    if (l == 0) { ss[w] = s; sq[w] = q; }
    __syncthreads();
    float ts = 0.f, tq = 0.f;
    #pragma unroll
    for (int i = 0; i < 8; i++) { ts += ss[i]; tq += sq[i]; }
    float mean = ts * (1.0f/512.0f);
    float var  = tq * (1.0f/512.0f) - mean*mean;
    float inv  = rsqrtf(var + 1e-5f);
    float v0 = (x0 - mean) * inv * gam[tid]       + bet[tid];
    float v1 = (x1 - mean) * inv * gam[tid + 256] + bet[tid + 256];
    float* o = out + (size_t)row * 512;
    o[tid]       = v0;
    o[tid + 256] = v1;
    if (oh) {
        oh[(size_t)row*512 + tid]       = __float2half(v0);
        oh[(size_t)row*512 + tid + 256] = __float2half(v1);
    }
}

// ---------------- input projection ------------------------------------------
__global__ __launch_bounds__(128)
void inproj_kernel(const float* __restrict__ feat, const float* __restrict__ w,
                   const float* __restrict__ bias, const float* __restrict__ pe,
                   float* __restrict__ out, __half* __restrict__ oh)
{
    int row = blockIdx.x;
    int t = row & (Tseq - 1);
    __shared__ float f[32];
    if (threadIdx.x < 32) f[threadIdx.x] = feat[(size_t)row*32 + threadIdx.x];
    __syncthreads();
    int d0 = threadIdx.x * 4;
    float a[4];
    #pragma unroll
    for (int j = 0; j < 4; j++) a[j] = bias[d0 + j];
    #pragma unroll
    for (int j = 0; j < 4; j++) {
        const float4* wp = (const float4*)(w + (size_t)(d0 + j) * 32);
        #pragma unroll
        for (int k4 = 0; k4 < 8; k4++) {
            float4 wv = wp[k4];
            a[j] += wv.x*f[k4*4] + wv.y*f[k4*4+1] + wv.z*f[k4*4+2] + wv.w*f[k4*4+3];
        }
    }
    float4 pev = *(const float4*)(pe + (size_t)t*512 + d0);
    float4 r = make_float4(a[0]+pev.x, a[1]+pev.y, a[2]+pev.z, a[3]+pev.w);
    *(float4*)(out + (size_t)row*512 + d0) = r;
    *(__half2*)(oh + (size_t)row*512 + d0)     = __floats2half2_rn(r.x, r.y);
    *(__half2*)(oh + (size_t)row*512 + d0 + 2) = __floats2half2_rn(r.z, r.w);
}

// ---------------- launch ----------------------------------------------------
extern "C" void kernel_launch(void* const* d_in, const int* in_sizes, int n_in,
                              void* d_out, int out_size)
{
    const float* feat   = (const float*)d_in[0];
    const float* proj_w = (const float*)d_in[2];
    const float* proj_b = (const float*)d_in[3];
    const float* pe     = (const float*)d_in[4];
    const float* qkv_w  = (const float*)d_in[5];
    const float* qkv_b  = (const float*)d_in[6];
    const float* out_w  = (const float*)d_in[7];
    const float* out_b  = (const float*)d_in[8];
    const float* ff1_w  = (const float*)d_in[9];
    const float* ff1_b  = (const float*)d_in[10];
    const float* ff2_w  = (const float*)d_in[11];
    const float* ff2_b  = (const float*)d_in[12];
    const float* ln1_g  = (const float*)d_in[13];
    const float* ln1_b  = (const float*)d_in[14];
    const float* ln2_g  = (const float*)d_in[15];
    const float* ln2_b  = (const float*)d_in[16];

    float *x, *y;
    __half *q, *xa, *a, *f, *wq, *wo, *w1, *w2;
    cudaGetSymbolAddress((void**)&x,  g_x);
    cudaGetSymbolAddress((void**)&y,  g_y);
    cudaGetSymbolAddress((void**)&q,  g_q);
    cudaGetSymbolAddress((void**)&xa, g_xa);
    cudaGetSymbolAddress((void**)&a,  g_a);
    cudaGetSymbolAddress((void**)&f,  g_f);
    cudaGetSymbolAddress((void**)&wq, g_wq);
    cudaGetSymbolAddress((void**)&wo, g_wo);
    cudaGetSymbolAddress((void**)&w1, g_w1);
    cudaGetSymbolAddress((void**)&w2, g_w2);

    cudaFuncSetAttribute(attn_flash, cudaFuncAttributeMaxDynamicSharedMemorySize, ATT_SMEM);
    cudaFuncSetAttribute(tc_gemm<0>, cudaFuncAttributeMaxDynamicSharedMemorySize, GS_TOTAL);
    cudaFuncSetAttribute(tc_gemm<1>, cudaFuncAttributeMaxDynamicSharedMemorySize, GS_TOTAL);
    cudaFuncSetAttribute(tc_gemm<2>, cudaFuncAttributeMaxDynamicSharedMemorySize, GS_TOTAL);
    cudaFuncSetAttribute(tc_gemm<3>, cudaFuncAttributeMaxDynamicSharedMemorySize, GS_TOTAL);

    {
        int n4;
        n4 = NLAYER*3*Dm*Dm/4; cvt4_kernel<<<(n4+255)/256,256>>>(qkv_w, wq, n4);
        n4 = NLAYER*Dm*Dm/4;   cvt4_kernel<<<(n4+255)/256,256>>>(out_w, wo, n4);
        n4 = NLAYER*FFd*Dm/4;  cvt4_kernel<<<(n4+255)/256,256>>>(ff1_w, w1, n4);
        n4 = NLAYER*Dm*FFd/4;  cvt4_kernel<<<(n4+255)/256,256>>>(ff2_w, w2, n4);
    }

    inproj_kernel<<<ROWS, 128>>>(feat, proj_w, proj_b, pe, x, xa);

    for (int l = 0; l < NLAYER; l++) {
        // QKV -> fp16
        tc_gemm<3><<<dim3(3*Dm/128, ROWS/128), 128, GS_TOTAL>>>(
            xa, wq + (size_t)l*3*Dm*Dm, qkv_b + (size_t)l*3*Dm, nullptr,
            nullptr, q, ROWS, 3*Dm, Dm);
        // flash banded attention -> a (fp16)
        attn_flash<<<dim3(Tseq/64, Hh, Bsz), 128, ATT_SMEM>>>(q, a);
        // out proj + residual(x) -> y
        tc_gemm<1><<<dim3(Dm/128, ROWS/128), 128, GS_TOTAL>>>(
            a, wo + (size_t)l*Dm*Dm, out_b + (size_t)l*Dm, x,
            y, nullptr, ROWS, Dm, Dm);
        ln_kernel<<<ROWS, 256>>>(y, ln1_g + (size_t)l*Dm, ln1_b + (size_t)l*Dm, x, xa);
        // FF1 + ReLU -> f (fp16)
        tc_gemm<2><<<dim3(FFd/128, ROWS/128), 128, GS_TOTAL>>>(
            xa, w1 + (size_t)l*FFd*Dm, ff1_b + (size_t)l*FFd, nullptr,
            nullptr, f, ROWS, FFd, Dm);
        // FF2 + residual(x) -> y
        tc_gemm<1><<<dim3(Dm/128, ROWS/128), 128, GS_TOTAL>>>(
            f, w2 + (size_t)l*Dm*FFd, ff2_b + (size_t)l*Dm, x,
            y, nullptr, ROWS, Dm, FFd);
        if (l == NLAYER - 1)
            ln_kernel<<<ROWS, 256>>>(y, ln2_g + (size_t)l*Dm, ln2_b + (size_t)l*Dm,
                                     (float*)d_out, nullptr);
        else
            ln_kernel<<<ROWS, 256>>>(y, ln2_g + (size_t)l*Dm, ln2_b + (size_t)l*Dm, x, xa);
    }
}